// round 1
// baseline (speedup 1.0000x reference)
#include <cuda_runtime.h>
#include <cstdint>

#define T_LEN 8192
#define CCH   512
#define BATCH 8
#define NELEM (BATCH * CCH * T_LEN)   // 33,554,432

// Scratch ping-pong buffers (no cudaMalloc allowed)
__device__ float g_buf1[NELEM];
__device__ float g_buf2[NELEM];

// ---------------------------------------------------------------------------
// Packed fp32x2 helpers (sm_100+): FFMA2 doubles fp32 FMA throughput
// ---------------------------------------------------------------------------
__device__ __forceinline__ unsigned long long pack2_dup(float v) {
    unsigned long long r;
    unsigned int u = __float_as_uint(v);
    asm("mov.b64 %0, {%1, %2};" : "=l"(r) : "r"(u), "r"(u));
    return r;
}
__device__ __forceinline__ void fma2(unsigned long long& d,
                                     unsigned long long a,
                                     unsigned long long b) {
    asm("fma.rn.f32x2 %0, %1, %2, %0;" : "+l"(d) : "l"(a), "l"(b));
}
__device__ __forceinline__ void unpack2(unsigned long long v, float& lo, float& hi) {
    unsigned int a, b;
    asm("mov.b64 {%0, %1}, %2;" : "=r"(a), "=r"(b) : "l"(v));
    lo = __uint_as_float(a);
    hi = __uint_as_float(b);
}

// ---------------------------------------------------------------------------
// Fused Activation1d: upsample(x2, FIR12, edge-pad) -> SnakeBeta -> downsample
// Derived closed form:
//   u[t'] (t' even) = 2*(f1*X(h+2)+f3*X(h+1)+f5*X(h)+f7*X(h-1)+f9*X(h-2)+f11*X(h-3)), h=t'/2
//   u[t'] (t' odd)  = 2*(f0*X(h)+f2*X(h-1)+f4*X(h-2)+f6*X(h-3)+f8*X(h-4)+f10*X(h-5)), h=(t'+5)/2
//   X(i) = x[clamp(i,0,T-1)]
//   v = u + sin(u*alpha)^2 / (beta + 1e-9)
//   z[t] = sum_k fd[k] * v[clamp(2t+k-5, 0, 2T-1)]
// One block: 256 outputs of one (b,c) row.
// ---------------------------------------------------------------------------
__global__ __launch_bounds__(256) void act_kernel(
    const float* __restrict__ in, float* __restrict__ out,
    const float* __restrict__ la, const float* __restrict__ lb,
    const float* __restrict__ fup, const float* __restrict__ fdn)
{
    __shared__ float sx[272];
    __shared__ float sv[524];
    __shared__ float su[12], sd[12];

    const int row = blockIdx.y;          // b*C + c
    const int c   = row & (CCH - 1);
    const int t0  = blockIdx.x * 256;
    const int tid = threadIdx.x;

    if (tid < 12) { su[tid] = fup[tid]; sd[tid] = fdn[tid]; }

    const float* xrow = in + (size_t)row * T_LEN;
    for (int i = tid; i < 272; i += 256) {
        int g = t0 - 8 + i;
        g = min(max(g, 0), T_LEN - 1);
        sx[i] = xrow[g];
    }
    __syncthreads();

    const float alpha = expf(la[c]);
    const float invb  = 1.0f / (expf(lb[c]) + 1e-9f);
    const int sx_off = 8 - t0;   // smem index = global_x_index + sx_off

    for (int i = tid; i < 522; i += 256) {
        const int tp = 2 * t0 - 5 + i;   // global t' (may be <0 / >=2T; unused then)
        float u;
        if (tp & 1) {
            const int h = (tp + 5) >> 1;           // exact: tp+5 even, >= 0
            const float* p = &sx[h + sx_off];
            u = su[0]*p[0] + su[2]*p[-1] + su[4]*p[-2]
              + su[6]*p[-3] + su[8]*p[-4] + su[10]*p[-5];
        } else {
            const int h = tp >> 1;                 // exact for even tp (arith shift)
            const float* p = &sx[h + sx_off];
            u = su[1]*p[2] + su[3]*p[1] + su[5]*p[0]
              + su[7]*p[-1] + su[9]*p[-2] + su[11]*p[-3];
        }
        u *= 2.0f;
        const float s = sinf(u * alpha);
        sv[i] = u + s * s * invb;
    }
    __syncthreads();

    const int t = t0 + tid;
    const int vbase = 2 * t - 5;
    const int soff  = -(2 * t0 - 5);
    float acc = 0.0f;
#pragma unroll
    for (int k = 0; k < 12; k++) {
        int vi = vbase + k;
        vi = min(max(vi, 0), 2 * T_LEN - 1);
        acc += sd[k] * sv[vi + soff];
    }
    out[(size_t)row * T_LEN + t] = acc;
}

// ---------------------------------------------------------------------------
// Depth-3 "same" conv, C=512 -> C=512, zero pad 1. Implicit GEMM:
//   out[co, t] = bias[co] + sum_{ci,k} w[co,ci,k] * in[ci, t+k-1]  (+ residual)
// Block tile: 128 co x 128 t, 256 threads, 8x8 micro-tile, f32x2 over co pairs.
// ---------------------------------------------------------------------------
__global__ __launch_bounds__(256) void conv_kernel(
    const float* __restrict__ in,      // [C][T] for batch b
    const float* __restrict__ w,       // [Cout][Cin][3]
    const float* __restrict__ bias,    // [Cout]
    const float* __restrict__ resid,   // [B][C][T] or nullptr
    float* __restrict__ out)           // [B][C][T]
{
    __shared__ __align__(16) float As[24 * 128];  // [(ci8*3+k)][co]  (12.0 KB)
    __shared__ __align__(16) float Bs[8 * 132];   // [ci8][tt 0..129], pad 132 (4.1 KB)

    const int tid = threadIdx.x;
    const int tx = tid & 15;        // t micro-tile index
    const int ty = tid >> 4;        // co micro-tile index
    const int b   = blockIdx.z;
    const int co0 = blockIdx.y * 128;
    const int t0  = blockIdx.x * 128;

    const float* inb = in + (size_t)b * CCH * T_LEN;

    unsigned long long acc[4][8];
#pragma unroll
    for (int i = 0; i < 4; i++)
#pragma unroll
        for (int j = 0; j < 8; j++) acc[i][j] = 0ULL;

    const int wco   = tid >> 1;       // 0..127
    const int whalf = tid & 1;        // 0..1

    for (int ci0 = 0; ci0 < CCH; ci0 += 8) {
        // ---- load weight tile: 128co x (8ci*3k) ----
        {
            const float* wp = w + (size_t)(co0 + wco) * (CCH * 3) + ci0 * 3 + whalf * 12;
            const float4 w0 = *reinterpret_cast<const float4*>(wp + 0);
            const float4 w1 = *reinterpret_cast<const float4*>(wp + 4);
            const float4 w2 = *reinterpret_cast<const float4*>(wp + 8);
            const int r = whalf * 12;
            As[(r + 0) * 128 + wco] = w0.x;  As[(r + 1) * 128 + wco] = w0.y;
            As[(r + 2) * 128 + wco] = w0.z;  As[(r + 3) * 128 + wco] = w0.w;
            As[(r + 4) * 128 + wco] = w1.x;  As[(r + 5) * 128 + wco] = w1.y;
            As[(r + 6) * 128 + wco] = w1.z;  As[(r + 7) * 128 + wco] = w1.w;
            As[(r + 8) * 128 + wco] = w2.x;  As[(r + 9) * 128 + wco] = w2.y;
            As[(r + 10) * 128 + wco] = w2.z; As[(r + 11) * 128 + wco] = w2.w;
        }
        // ---- load input tile: 8ci x 130t (t0-1 .. t0+128), zero-padded ----
        for (int idx = tid; idx < 8 * 130; idx += 256) {
            const int ci = idx / 130;
            const int tt = idx - ci * 130;
            const int tg = t0 - 1 + tt;
            float v = 0.0f;
            if (tg >= 0 && tg < T_LEN)
                v = inb[(size_t)(ci0 + ci) * T_LEN + tg];
            Bs[ci * 132 + tt] = v;
        }
        __syncthreads();

#pragma unroll
        for (int ci = 0; ci < 8; ci++) {
            // 10-wide input window for this thread's 8 t's (taps k=0..2)
            float bxf[10];
            {
                const float4 b0 = *reinterpret_cast<const float4*>(&Bs[ci * 132 + tx * 8]);
                const float4 b1 = *reinterpret_cast<const float4*>(&Bs[ci * 132 + tx * 8 + 4]);
                const float2 b2 = *reinterpret_cast<const float2*>(&Bs[ci * 132 + tx * 8 + 8]);
                bxf[0] = b0.x; bxf[1] = b0.y; bxf[2] = b0.z; bxf[3] = b0.w;
                bxf[4] = b1.x; bxf[5] = b1.y; bxf[6] = b1.z; bxf[7] = b1.w;
                bxf[8] = b2.x; bxf[9] = b2.y;
            }
            unsigned long long bx2[10];
#pragma unroll
            for (int j = 0; j < 10; j++) bx2[j] = pack2_dup(bxf[j]);

#pragma unroll
            for (int k = 0; k < 3; k++) {
                const unsigned long long* ap =
                    reinterpret_cast<const unsigned long long*>(&As[(ci * 3 + k) * 128 + ty * 8]);
                unsigned long long a0 = ap[0], a1 = ap[1], a2 = ap[2], a3 = ap[3];
#pragma unroll
                for (int j = 0; j < 8; j++) {
                    fma2(acc[0][j], a0, bx2[j + k]);
                    fma2(acc[1][j], a1, bx2[j + k]);
                    fma2(acc[2][j], a2, bx2[j + k]);
                    fma2(acc[3][j], a3, bx2[j + k]);
                }
            }
        }
        __syncthreads();
    }

    // ---- epilogue: unpack, add bias (+ residual), store ----
#pragma unroll
    for (int i2 = 0; i2 < 4; i2++) {
        const int co = co0 + ty * 8 + 2 * i2;
        const float blo = bias[co];
        const float bhi = bias[co + 1];
        float* orow_lo = out + ((size_t)b * CCH + co) * T_LEN;
        float* orow_hi = orow_lo + T_LEN;
        const float* rrow_lo = resid ? resid + ((size_t)b * CCH + co) * T_LEN : nullptr;
#pragma unroll
        for (int j = 0; j < 8; j++) {
            const int t = t0 + tx * 8 + j;
            float lo, hi;
            unpack2(acc[i2][j], lo, hi);
            lo += blo; hi += bhi;
            if (rrow_lo) { lo += rrow_lo[t]; hi += rrow_lo[T_LEN + t]; }
            orow_lo[t] = lo;
            orow_hi[t] = hi;
        }
    }
}

// ---------------------------------------------------------------------------
extern "C" void kernel_launch(void* const* d_in, const int* in_sizes, int n_in,
                              void* d_out, int out_size)
{
    const float* x    = (const float*)d_in[0];
    const float* a1a  = (const float*)d_in[1];
    const float* a1b  = (const float*)d_in[2];
    const float* a2a  = (const float*)d_in[3];
    const float* a2b  = (const float*)d_in[4];
    const float* c1w  = (const float*)d_in[5];
    const float* c1b  = (const float*)d_in[6];
    const float* c2w  = (const float*)d_in[7];
    const float* c2b  = (const float*)d_in[8];
    const float* fup  = (const float*)d_in[9];
    const float* fdn  = (const float*)d_in[10];
    float* out = (float*)d_out;

    float *g1, *g2;
    cudaGetSymbolAddress((void**)&g1, g_buf1);
    cudaGetSymbolAddress((void**)&g2, g_buf2);

    dim3 gAct(T_LEN / 256, BATCH * CCH);
    dim3 gConv(T_LEN / 128, CCH / 128, BATCH);

    // act1: x -> g1
    act_kernel<<<gAct, 256>>>(x, g1, a1a, a1b, fup, fdn);
    // conv1: g1 -> g2
    conv_kernel<<<gConv, 256>>>(g1, c1w, c1b, nullptr, g2);
    // act2: g2 -> g1
    act_kernel<<<gAct, 256>>>(g2, g1, a2a, a2b, fup, fdn);
    // conv2 + residual: g1 -> out
    conv_kernel<<<gConv, 256>>>(g1, c2w, c2b, x, out);
}

// round 2
// speedup vs baseline: 1.0006x; 1.0006x over previous
#include <cuda_runtime.h>
#include <cstdint>

#define T_LEN 8192
#define CCH   512
#define BATCH 8
#define NELEM (BATCH * CCH * T_LEN)   // 33,554,432

// Scratch ping-pong buffers (no cudaMalloc allowed)
__device__ float g_buf1[NELEM];
__device__ float g_buf2[NELEM];

// ---------------------------------------------------------------------------
// Packed fp32x2 helpers (sm_100+): FFMA2 doubles fp32 FMA throughput
// ---------------------------------------------------------------------------
__device__ __forceinline__ unsigned long long pack2_dup(float v) {
    unsigned long long r;
    unsigned int u = __float_as_uint(v);
    asm("mov.b64 %0, {%1, %2};" : "=l"(r) : "r"(u), "r"(u));
    return r;
}
__device__ __forceinline__ void fma2(unsigned long long& d,
                                     unsigned long long a,
                                     unsigned long long b) {
    asm("fma.rn.f32x2 %0, %1, %2, %0;" : "+l"(d) : "l"(a), "l"(b));
}
__device__ __forceinline__ void unpack2(unsigned long long v, float& lo, float& hi) {
    unsigned int a, b;
    asm("mov.b64 {%0, %1}, %2;" : "=r"(a), "=r"(b) : "l"(v));
    lo = __uint_as_float(a);
    hi = __uint_as_float(b);
}

// ---------------------------------------------------------------------------
// Fused Activation1d: upsample(x2, FIR12, edge-pad) -> SnakeBeta -> downsample
// Derived closed form:
//   u[t'] (t' even) = 2*(f1*X(h+2)+f3*X(h+1)+f5*X(h)+f7*X(h-1)+f9*X(h-2)+f11*X(h-3)), h=t'/2
//   u[t'] (t' odd)  = 2*(f0*X(h)+f2*X(h-1)+f4*X(h-2)+f6*X(h-3)+f8*X(h-4)+f10*X(h-5)), h=(t'+5)/2
//   X(i) = x[clamp(i,0,T-1)]
//   v = u + sin(u*alpha)^2 / (beta + 1e-9)
//   z[t] = sum_k fd[k] * v[clamp(2t+k-5, 0, 2T-1)]
// One block: 256 outputs of one (b,c) row.
// ---------------------------------------------------------------------------
__global__ __launch_bounds__(256) void act_kernel(
    const float* __restrict__ in, float* __restrict__ out,
    const float* __restrict__ la, const float* __restrict__ lb,
    const float* __restrict__ fup, const float* __restrict__ fdn)
{
    __shared__ float sx[272];
    __shared__ float sv[524];
    __shared__ float su[12], sd[12];

    const int row = blockIdx.y;          // b*C + c
    const int c   = row & (CCH - 1);
    const int t0  = blockIdx.x * 256;
    const int tid = threadIdx.x;

    if (tid < 12) { su[tid] = fup[tid]; sd[tid] = fdn[tid]; }

    const float* xrow = in + (size_t)row * T_LEN;
    for (int i = tid; i < 272; i += 256) {
        int g = t0 - 8 + i;
        g = min(max(g, 0), T_LEN - 1);
        sx[i] = xrow[g];
    }
    __syncthreads();

    const float alpha = expf(la[c]);
    const float invb  = 1.0f / (expf(lb[c]) + 1e-9f);
    const int sx_off = 8 - t0;   // smem index = global_x_index + sx_off

    for (int i = tid; i < 522; i += 256) {
        const int tp = 2 * t0 - 5 + i;   // global t' (may be <0 / >=2T; unused then)
        float u;
        if (tp & 1) {
            const int h = (tp + 5) >> 1;           // exact: tp+5 even, >= 0
            const float* p = &sx[h + sx_off];
            u = su[0]*p[0] + su[2]*p[-1] + su[4]*p[-2]
              + su[6]*p[-3] + su[8]*p[-4] + su[10]*p[-5];
        } else {
            const int h = tp >> 1;                 // exact for even tp (arith shift)
            const float* p = &sx[h + sx_off];
            u = su[1]*p[2] + su[3]*p[1] + su[5]*p[0]
              + su[7]*p[-1] + su[9]*p[-2] + su[11]*p[-3];
        }
        u *= 2.0f;
        const float s = sinf(u * alpha);
        sv[i] = u + s * s * invb;
    }
    __syncthreads();

    const int t = t0 + tid;
    const int vbase = 2 * t - 5;
    const int soff  = -(2 * t0 - 5);
    float acc = 0.0f;
#pragma unroll
    for (int k = 0; k < 12; k++) {
        int vi = vbase + k;
        vi = min(max(vi, 0), 2 * T_LEN - 1);
        acc += sd[k] * sv[vi + soff];
    }
    out[(size_t)row * T_LEN + t] = acc;
}

// ---------------------------------------------------------------------------
// Depth-3 "same" conv, C=512 -> C=512, zero pad 1. Implicit GEMM:
//   out[co, t] = bias[co] + sum_{ci,k} w[co,ci,k] * in[ci, t+k-1]  (+ residual)
// Block tile: 128 co x 128 t, 256 threads, 8x8 micro-tile, f32x2 over co pairs.
// ---------------------------------------------------------------------------
__global__ __launch_bounds__(256) void conv_kernel(
    const float* __restrict__ in,      // [C][T] for batch b
    const float* __restrict__ w,       // [Cout][Cin][3]
    const float* __restrict__ bias,    // [Cout]
    const float* __restrict__ resid,   // [B][C][T] or nullptr
    float* __restrict__ out)           // [B][C][T]
{
    __shared__ __align__(16) float As[24 * 128];  // [(ci8*3+k)][co]  (12.0 KB)
    __shared__ __align__(16) float Bs[8 * 132];   // [ci8][tt 0..129], pad 132 (4.1 KB)

    const int tid = threadIdx.x;
    const int tx = tid & 15;        // t micro-tile index
    const int ty = tid >> 4;        // co micro-tile index
    const int b   = blockIdx.z;
    const int co0 = blockIdx.y * 128;
    const int t0  = blockIdx.x * 128;

    const float* inb = in + (size_t)b * CCH * T_LEN;

    unsigned long long acc[4][8];
#pragma unroll
    for (int i = 0; i < 4; i++)
#pragma unroll
        for (int j = 0; j < 8; j++) acc[i][j] = 0ULL;

    const int wco   = tid >> 1;       // 0..127
    const int whalf = tid & 1;        // 0..1

    for (int ci0 = 0; ci0 < CCH; ci0 += 8) {
        // ---- load weight tile: 128co x (8ci*3k) ----
        {
            const float* wp = w + (size_t)(co0 + wco) * (CCH * 3) + ci0 * 3 + whalf * 12;
            const float4 w0 = *reinterpret_cast<const float4*>(wp + 0);
            const float4 w1 = *reinterpret_cast<const float4*>(wp + 4);
            const float4 w2 = *reinterpret_cast<const float4*>(wp + 8);
            const int r = whalf * 12;
            As[(r + 0) * 128 + wco] = w0.x;  As[(r + 1) * 128 + wco] = w0.y;
            As[(r + 2) * 128 + wco] = w0.z;  As[(r + 3) * 128 + wco] = w0.w;
            As[(r + 4) * 128 + wco] = w1.x;  As[(r + 5) * 128 + wco] = w1.y;
            As[(r + 6) * 128 + wco] = w1.z;  As[(r + 7) * 128 + wco] = w1.w;
            As[(r + 8) * 128 + wco] = w2.x;  As[(r + 9) * 128 + wco] = w2.y;
            As[(r + 10) * 128 + wco] = w2.z; As[(r + 11) * 128 + wco] = w2.w;
        }
        // ---- load input tile: 8ci x 130t (t0-1 .. t0+128), zero-padded ----
        for (int idx = tid; idx < 8 * 130; idx += 256) {
            const int ci = idx / 130;
            const int tt = idx - ci * 130;
            const int tg = t0 - 1 + tt;
            float v = 0.0f;
            if (tg >= 0 && tg < T_LEN)
                v = inb[(size_t)(ci0 + ci) * T_LEN + tg];
            Bs[ci * 132 + tt] = v;
        }
        __syncthreads();

#pragma unroll
        for (int ci = 0; ci < 8; ci++) {
            // 10-wide input window for this thread's 8 t's (taps k=0..2)
            float bxf[10];
            {
                const float4 b0 = *reinterpret_cast<const float4*>(&Bs[ci * 132 + tx * 8]);
                const float4 b1 = *reinterpret_cast<const float4*>(&Bs[ci * 132 + tx * 8 + 4]);
                const float2 b2 = *reinterpret_cast<const float2*>(&Bs[ci * 132 + tx * 8 + 8]);
                bxf[0] = b0.x; bxf[1] = b0.y; bxf[2] = b0.z; bxf[3] = b0.w;
                bxf[4] = b1.x; bxf[5] = b1.y; bxf[6] = b1.z; bxf[7] = b1.w;
                bxf[8] = b2.x; bxf[9] = b2.y;
            }
            unsigned long long bx2[10];
#pragma unroll
            for (int j = 0; j < 10; j++) bx2[j] = pack2_dup(bxf[j]);

#pragma unroll
            for (int k = 0; k < 3; k++) {
                const unsigned long long* ap =
                    reinterpret_cast<const unsigned long long*>(&As[(ci * 3 + k) * 128 + ty * 8]);
                unsigned long long a0 = ap[0], a1 = ap[1], a2 = ap[2], a3 = ap[3];
#pragma unroll
                for (int j = 0; j < 8; j++) {
                    fma2(acc[0][j], a0, bx2[j + k]);
                    fma2(acc[1][j], a1, bx2[j + k]);
                    fma2(acc[2][j], a2, bx2[j + k]);
                    fma2(acc[3][j], a3, bx2[j + k]);
                }
            }
        }
        __syncthreads();
    }

    // ---- epilogue: unpack, add bias (+ residual), store ----
#pragma unroll
    for (int i2 = 0; i2 < 4; i2++) {
        const int co = co0 + ty * 8 + 2 * i2;
        const float blo = bias[co];
        const float bhi = bias[co + 1];
        float* orow_lo = out + ((size_t)b * CCH + co) * T_LEN;
        float* orow_hi = orow_lo + T_LEN;
        const float* rrow_lo = resid ? resid + ((size_t)b * CCH + co) * T_LEN : nullptr;
#pragma unroll
        for (int j = 0; j < 8; j++) {
            const int t = t0 + tx * 8 + j;
            float lo, hi;
            unpack2(acc[i2][j], lo, hi);
            lo += blo; hi += bhi;
            if (rrow_lo) { lo += rrow_lo[t]; hi += rrow_lo[T_LEN + t]; }
            orow_lo[t] = lo;
            orow_hi[t] = hi;
        }
    }
}

// ---------------------------------------------------------------------------
extern "C" void kernel_launch(void* const* d_in, const int* in_sizes, int n_in,
                              void* d_out, int out_size)
{
    const float* x    = (const float*)d_in[0];
    const float* a1a  = (const float*)d_in[1];
    const float* a1b  = (const float*)d_in[2];
    const float* a2a  = (const float*)d_in[3];
    const float* a2b  = (const float*)d_in[4];
    const float* c1w  = (const float*)d_in[5];
    const float* c1b  = (const float*)d_in[6];
    const float* c2w  = (const float*)d_in[7];
    const float* c2b  = (const float*)d_in[8];
    const float* fup  = (const float*)d_in[9];
    const float* fdn  = (const float*)d_in[10];
    float* out = (float*)d_out;

    float *g1, *g2;
    cudaGetSymbolAddress((void**)&g1, g_buf1);
    cudaGetSymbolAddress((void**)&g2, g_buf2);

    dim3 gAct(T_LEN / 256, BATCH * CCH);
    dim3 gConv(T_LEN / 128, CCH / 128, BATCH);

    // act1: x -> g1
    act_kernel<<<gAct, 256>>>(x, g1, a1a, a1b, fup, fdn);
    // conv1: g1 -> g2
    conv_kernel<<<gConv, 256>>>(g1, c1w, c1b, nullptr, g2);
    // act2: g2 -> g1
    act_kernel<<<gAct, 256>>>(g2, g1, a2a, a2b, fup, fdn);
    // conv2 + residual: g1 -> out
    conv_kernel<<<gConv, 256>>>(g1, c2w, c2b, x, out);
}

// round 4
// speedup vs baseline: 1.2291x; 1.2283x over previous
#include <cuda_runtime.h>
#include <cstdint>

#define T_LEN 8192
#define CCH   512
#define BATCH 8
#define NELEM (BATCH * CCH * T_LEN)

__device__ float g_buf1[NELEM];
__device__ float g_buf2[NELEM];

// ---------------------------------------------------------------------------
// helpers
// ---------------------------------------------------------------------------
__device__ __forceinline__ uint32_t f2tf(float f) {
    uint32_t r;
    asm("cvt.rn.tf32.f32 %0, %1;" : "=r"(r) : "f"(f));
    return r;
}

// mma.sync m16n8k8 tf32, row.col, f32 accum (plain sm_80+ PTX, no "a" gating)
__device__ __forceinline__ void mma_tf32(float* d, const uint32_t* a, const uint32_t* b) {
    asm volatile(
        "mma.sync.aligned.m16n8k8.row.col.f32.tf32.tf32.f32 "
        "{%0,%1,%2,%3}, {%4,%5,%6,%7}, {%8,%9}, {%0,%1,%2,%3};"
        : "+f"(d[0]), "+f"(d[1]), "+f"(d[2]), "+f"(d[3])
        : "r"(a[0]), "r"(a[1]), "r"(a[2]), "r"(a[3]), "r"(b[0]), "r"(b[1]));
}

// ---------------------------------------------------------------------------
// Fused Activation1d: up(x2, FIR12, edge) -> SnakeBeta -> down(x2, FIR12, edge)
// ---------------------------------------------------------------------------
__global__ __launch_bounds__(256) void act_kernel(
    const float* __restrict__ in, float* __restrict__ out,
    const float* __restrict__ la, const float* __restrict__ lb,
    const float* __restrict__ fup, const float* __restrict__ fdn)
{
    __shared__ float sx[272];
    __shared__ float sv[524];
    __shared__ float su[12], sd[12];

    const int row = blockIdx.y;
    const int c   = row & (CCH - 1);
    const int t0  = blockIdx.x * 256;
    const int tid = threadIdx.x;

    if (tid < 12) { su[tid] = fup[tid]; sd[tid] = fdn[tid]; }

    const float* xrow = in + (size_t)row * T_LEN;
    for (int i = tid; i < 272; i += 256) {
        int g = t0 - 8 + i;
        g = min(max(g, 0), T_LEN - 1);
        sx[i] = xrow[g];
    }
    __syncthreads();

    const float alpha = expf(la[c]);
    const float invb  = 1.0f / (expf(lb[c]) + 1e-9f);
    const int sx_off = 8 - t0;

    for (int i = tid; i < 522; i += 256) {
        const int tp = 2 * t0 - 5 + i;
        float u;
        if (tp & 1) {
            const int h = (tp + 5) >> 1;
            const float* p = &sx[h + sx_off];
            u = su[0]*p[0] + su[2]*p[-1] + su[4]*p[-2]
              + su[6]*p[-3] + su[8]*p[-4] + su[10]*p[-5];
        } else {
            const int h = tp >> 1;
            const float* p = &sx[h + sx_off];
            u = su[1]*p[2] + su[3]*p[1] + su[5]*p[0]
              + su[7]*p[-1] + su[9]*p[-2] + su[11]*p[-3];
        }
        u *= 2.0f;
        const float s = __sinf(u * alpha);
        sv[i] = u + s * s * invb;
    }
    __syncthreads();

    const int t = t0 + tid;
    const int vbase = 2 * t - 5;
    const int soff  = -(2 * t0 - 5);
    float acc = 0.0f;
#pragma unroll
    for (int k = 0; k < 12; k++) {
        int vi = vbase + k;
        vi = min(max(vi, 0), 2 * T_LEN - 1);
        acc += sd[k] * sv[vi + soff];
    }
    out[(size_t)row * T_LEN + t] = acc;
}

// ---------------------------------------------------------------------------
// tf32 HMMA implicit-GEMM conv:
//   D[co][t] = bias[co] + sum_{k=ci*3+kk} W[co][k] * X[ci][t+kk-1]  (+ resid)
// Block 128co x 128t, 8 warps (2x4: warp tile 64x32), K in 48 chunks of 32.
// smem holds tiles pre-permuted into mma fragment order:
//   A frags: [kstep(4)][mtile(8)][lane(32)][4]  (uint4 per lane)
//   B frags: [kstep(4)][n8(16)][lane(32)][2]    (uint2 per lane)
// Double-buffered (2 x 32KB), one __syncthreads per chunk.
// ---------------------------------------------------------------------------
#define KCHUNKS 48
#define STAGE_U32 8192           // 32KB per stage (4096 A + 4096 B words)
#define DYN_SMEM (2 * STAGE_U32 * 4)

__global__ __launch_bounds__(256, 1)
void conv_tc(const float* __restrict__ in, const float* __restrict__ w,
             const float* __restrict__ bias, const float* __restrict__ resid,
             float* __restrict__ out)
{
    extern __shared__ uint32_t smem[];

    const int tid  = threadIdx.x;
    const int wid  = tid >> 5;
    const int lane = tid & 31;
    const int wr   = wid >> 2;       // warp row: M offset 64*wr
    const int wc   = wid & 3;        // warp col: N offset 32*wc
    const int b    = blockIdx.z;
    const int co0  = blockIdx.y * 128;
    const int t0   = blockIdx.x * 128;
    const float* inb = in + (size_t)b * CCH * T_LEN;

    // fill thread mapping
    const int wco   = tid >> 1;      // A: co row 0..127
    const int whalf = tid & 1;       // A: k half (16 each)
    const int kb    = tid >> 3;      // B: k col 0..31
    const int ng    = tid & 7;       // B: n group (16 each)

    float acc[4][4][4];
#pragma unroll
    for (int i = 0; i < 4; i++)
#pragma unroll
        for (int j = 0; j < 4; j++)
#pragma unroll
            for (int r = 0; r < 4; r++) acc[i][j][r] = 0.0f;

    auto fill = [&](int q, int s) {
        uint32_t* st = smem + s * STAGE_U32;
        const int k0 = q * 32;
        // ---- A: w[co0+wco][k0 + whalf*16 + j], scatter to fragment order ----
        {
            const float* wp = w + (size_t)(co0 + wco) * 1536 + k0 + whalf * 16;
            float va[16];
#pragma unroll
            for (int j4 = 0; j4 < 4; ++j4) {
                float4 v = *reinterpret_cast<const float4*>(wp + j4 * 4);
                va[j4*4+0] = v.x; va[j4*4+1] = v.y; va[j4*4+2] = v.z; va[j4*4+3] = v.w;
            }
            const int mtile = wco >> 4;
            const int m8    = wco & 15;
#pragma unroll
            for (int j = 0; j < 16; ++j) {
                const int k  = whalf * 16 + j;
                const int ks = k >> 3, kk = k & 7;
                const int ln = (m8 & 7) * 4 + (kk & 3);
                const int rg = (m8 >> 3) + 2 * (kk >> 2);
                st[(ks * 8 + mtile) * 128 + ln * 4 + rg] = f2tf(va[j]);
            }
        }
        // ---- B: im2col X[ci][t0 + n + kk3 - 1], scatter to fragment order ----
        {
            const int k  = k0 + kb;
            const int ci = k / 3;
            const int kk3 = k - ci * 3;
            const float* xr = inb + (size_t)ci * T_LEN;
            const int tb = t0 + ng * 16 + kk3 - 1;
            const int ks = kb >> 3, kk8 = kb & 7;
            const int rg = kk8 >> 2;
            uint32_t* bst = st + 4096;
#pragma unroll
            for (int j = 0; j < 16; ++j) {
                const int tg = tb + j;
                float v = 0.0f;
                if (tg >= 0 && tg < T_LEN) v = __ldg(xr + tg);
                const int n  = ng * 16 + j;
                const int ln = (n & 7) * 4 + (kk8 & 3);
                bst[(ks * 16 + (n >> 3)) * 64 + ln * 2 + rg] = f2tf(v);
            }
        }
    };

    fill(0, 0);
    __syncthreads();

    for (int q = 0; q < KCHUNKS; ++q) {
        const int s = q & 1;
        if (q + 1 < KCHUNKS) fill(q + 1, s ^ 1);

        const uint32_t* Asm = smem + s * STAGE_U32;
        const uint32_t* Bsm = Asm + 4096;
#pragma unroll
        for (int ks = 0; ks < 4; ++ks) {
            uint4 afr[4];
            uint2 bfr[4];
#pragma unroll
            for (int mt = 0; mt < 4; ++mt)
                afr[mt] = *reinterpret_cast<const uint4*>(
                    Asm + (ks * 8 + wr * 4 + mt) * 128 + lane * 4);
#pragma unroll
            for (int nt = 0; nt < 4; ++nt)
                bfr[nt] = *reinterpret_cast<const uint2*>(
                    Bsm + (ks * 16 + wc * 4 + nt) * 64 + lane * 2);
#pragma unroll
            for (int mt = 0; mt < 4; ++mt)
#pragma unroll
                for (int nt = 0; nt < 4; ++nt)
                    mma_tf32(acc[mt][nt],
                             reinterpret_cast<const uint32_t*>(&afr[mt]),
                             reinterpret_cast<const uint32_t*>(&bfr[nt]));
        }
        __syncthreads();
    }

    // ---- epilogue ----
    const int gid = lane >> 2;       // 0..7
    const int tig = lane & 3;        // 0..3
#pragma unroll
    for (int mt = 0; mt < 4; ++mt) {
#pragma unroll
        for (int half = 0; half < 2; ++half) {
            const int co = co0 + wr * 64 + mt * 16 + gid + half * 8;
            const float bv = bias[co];
            float* orow = out + ((size_t)b * CCH + co) * T_LEN + t0 + wc * 32;
            const float* rrow = resid
                ? resid + ((size_t)b * CCH + co) * T_LEN + t0 + wc * 32 : nullptr;
#pragma unroll
            for (int nt = 0; nt < 4; ++nt) {
                const int n = nt * 8 + tig * 2;
                float lo = acc[mt][nt][half * 2 + 0] + bv;
                float hi = acc[mt][nt][half * 2 + 1] + bv;
                if (rrow) {
                    float2 rv = *reinterpret_cast<const float2*>(rrow + n);
                    lo += rv.x; hi += rv.y;
                }
                float2 v; v.x = lo; v.y = hi;
                *reinterpret_cast<float2*>(orow + n) = v;
            }
        }
    }
}

// ---------------------------------------------------------------------------
extern "C" void kernel_launch(void* const* d_in, const int* in_sizes, int n_in,
                              void* d_out, int out_size)
{
    const float* x    = (const float*)d_in[0];
    const float* a1a  = (const float*)d_in[1];
    const float* a1b  = (const float*)d_in[2];
    const float* a2a  = (const float*)d_in[3];
    const float* a2b  = (const float*)d_in[4];
    const float* c1w  = (const float*)d_in[5];
    const float* c1b  = (const float*)d_in[6];
    const float* c2w  = (const float*)d_in[7];
    const float* c2b  = (const float*)d_in[8];
    const float* fup  = (const float*)d_in[9];
    const float* fdn  = (const float*)d_in[10];
    float* out = (float*)d_out;

    float *g1, *g2;
    cudaGetSymbolAddress((void**)&g1, g_buf1);
    cudaGetSymbolAddress((void**)&g2, g_buf2);

    static int smem_set = 0;
    if (!smem_set) {
        cudaFuncSetAttribute(conv_tc, cudaFuncAttributeMaxDynamicSharedMemorySize, DYN_SMEM);
        smem_set = 1;
    }

    dim3 gAct(T_LEN / 256, BATCH * CCH);
    dim3 gConv(T_LEN / 128, CCH / 128, BATCH);

    act_kernel<<<gAct, 256>>>(x, g1, a1a, a1b, fup, fdn);
    conv_tc<<<gConv, 256, DYN_SMEM>>>(g1, c1w, c1b, nullptr, g2);
    act_kernel<<<gAct, 256>>>(g2, g1, a2a, a2b, fup, fdn);
    conv_tc<<<gConv, 256, DYN_SMEM>>>(g1, c2w, c2b, x, out);
}

// round 5
// speedup vs baseline: 2.6908x; 2.1893x over previous
#include <cuda_runtime.h>
#include <cstdint>

#define T_LEN 8192
#define CCH   512
#define BATCH 8
#define NELEM (BATCH * CCH * T_LEN)

__device__ float g_buf1[NELEM];
__device__ float g_buf2[NELEM];

// Pre-permuted weights in mma-fragment order: [cb(4)][q(48)][frow(32)][lane(32)][4]
#define WPERM_U32 (4 * 48 * 32 * 32 * 4)   // 786432 words = 3 MB
__device__ uint32_t g_wperm1[WPERM_U32];
__device__ uint32_t g_wperm2[WPERM_U32];

// ---------------------------------------------------------------------------
__device__ __forceinline__ uint32_t f2tf(float f) {
    uint32_t r;
    asm("cvt.rn.tf32.f32 %0, %1;" : "=r"(r) : "f"(f));
    return r;
}
__device__ __forceinline__ void mma_tf32(float* d, const uint32_t* a, const uint32_t* b) {
    asm volatile(
        "mma.sync.aligned.m16n8k8.row.col.f32.tf32.tf32.f32 "
        "{%0,%1,%2,%3}, {%4,%5,%6,%7}, {%8,%9}, {%0,%1,%2,%3};"
        : "+f"(d[0]), "+f"(d[1]), "+f"(d[2]), "+f"(d[3])
        : "r"(a[0]), "r"(a[1]), "r"(a[2]), "r"(a[3]), "r"(b[0]), "r"(b[1]));
}

// ---------------------------------------------------------------------------
// Weight permutation: w[co][k] (k = ci*3+kk, K=1536) -> fragment order.
// frow = ks*8 + mt;  lane holds a0..a3 per m16n8k8 tf32 spec:
//   rg: m8 = (lane>>2) + 8*(rg&1), kk = (lane&3) + 4*(rg>>1)
// ---------------------------------------------------------------------------
__global__ __launch_bounds__(256) void permute_w(
    const float* __restrict__ w, uint32_t* __restrict__ wp)
{
    const int tid = blockIdx.x * 256 + threadIdx.x;    // 0..196607
    const int lane = tid & 31;
    const int frow = (tid >> 5) & 31;
    const int rest = tid >> 10;                        // cb*48 + q
    const int q  = rest % 48;
    const int cb = rest / 48;
    const int ks = frow >> 3;
    const int mt = frow & 7;

    uint4 v;
    uint32_t* o = &v.x;
#pragma unroll
    for (int rg = 0; rg < 4; ++rg) {
        const int m8 = (lane >> 2) + 8 * (rg & 1);
        const int kk = (lane & 3) + 4 * (rg >> 1);
        const int co = cb * 128 + mt * 16 + m8;
        const int k  = q * 32 + ks * 8 + kk;
        o[rg] = f2tf(w[(size_t)co * 1536 + k]);
    }
    reinterpret_cast<uint4*>(wp)[tid] = v;
}

// ---------------------------------------------------------------------------
// Fused Activation1d
// ---------------------------------------------------------------------------
__global__ __launch_bounds__(256) void act_kernel(
    const float* __restrict__ in, float* __restrict__ out,
    const float* __restrict__ la, const float* __restrict__ lb,
    const float* __restrict__ fup, const float* __restrict__ fdn)
{
    __shared__ float sx[272];
    __shared__ float sv[524];
    __shared__ float su[12], sd[12];

    const int row = blockIdx.y;
    const int c   = row & (CCH - 1);
    const int t0  = blockIdx.x * 256;
    const int tid = threadIdx.x;

    if (tid < 12) { su[tid] = fup[tid]; sd[tid] = fdn[tid]; }

    const float* xrow = in + (size_t)row * T_LEN;
    for (int i = tid; i < 272; i += 256) {
        int g = t0 - 8 + i;
        g = min(max(g, 0), T_LEN - 1);
        sx[i] = xrow[g];
    }
    __syncthreads();

    const float alpha = expf(la[c]);
    const float invb  = 1.0f / (expf(lb[c]) + 1e-9f);
    const int sx_off = 8 - t0;

    for (int i = tid; i < 522; i += 256) {
        const int tp = 2 * t0 - 5 + i;
        float u;
        if (tp & 1) {
            const int h = (tp + 5) >> 1;
            const float* p = &sx[h + sx_off];
            u = su[0]*p[0] + su[2]*p[-1] + su[4]*p[-2]
              + su[6]*p[-3] + su[8]*p[-4] + su[10]*p[-5];
        } else {
            const int h = tp >> 1;
            const float* p = &sx[h + sx_off];
            u = su[1]*p[2] + su[3]*p[1] + su[5]*p[0]
              + su[7]*p[-1] + su[9]*p[-2] + su[11]*p[-3];
        }
        u *= 2.0f;
        const float s = __sinf(u * alpha);
        sv[i] = u + s * s * invb;
    }
    __syncthreads();

    const int t = t0 + tid;
    const int vbase = 2 * t - 5;
    const int soff  = -(2 * t0 - 5);
    float acc = 0.0f;
#pragma unroll
    for (int k = 0; k < 12; k++) {
        int vi = vbase + k;
        vi = min(max(vi, 0), 2 * T_LEN - 1);
        acc += sd[k] * sv[vi + soff];
    }
    out[(size_t)row * T_LEN + t] = acc;
}

// ---------------------------------------------------------------------------
// tf32 HMMA implicit-GEMM conv. Block 128co x 128t, 8 warps (2x4).
// A: fragment-order gmem (LDG.128 direct, no smem).
// B: natural [k(32)][t(128)] smem, pitch 136 words (conflict-free STS/LDS).
// ---------------------------------------------------------------------------
#define KCHUNKS 48
#define BPITCH 136
#define BSTAGE (32 * BPITCH)     // 4352 words = 17408 B

__global__ __launch_bounds__(256, 2)
void conv_tc(const float* __restrict__ in, const uint32_t* __restrict__ wperm,
             const float* __restrict__ bias, const float* __restrict__ resid,
             float* __restrict__ out)
{
    __shared__ uint32_t Bsm[2 * BSTAGE];

    const int tid  = threadIdx.x;
    const int wid  = tid >> 5;
    const int lane = tid & 31;
    const int wr   = wid >> 2;       // 0..1: M offset 64*wr
    const int wc   = wid & 3;        // 0..3: N offset 32*wc
    const int b    = blockIdx.z;
    const int cb   = blockIdx.y;     // co block (4)
    const int co0  = cb * 128;
    const int t0   = blockIdx.x * 128;
    const float* inb = in + (size_t)b * CCH * T_LEN;

    float acc[4][4][4];
#pragma unroll
    for (int i = 0; i < 4; i++)
#pragma unroll
        for (int j = 0; j < 4; j++)
#pragma unroll
            for (int r = 0; r < 4; r++) acc[i][j][r] = 0.0f;

    // B fill: iter j covers k rows; warp = 32 consecutive t (coalesced LDG,
    // conflict-free STS at k*136 + t).
    const int ftt = tid & 127;          // t index
    const int fjh = tid >> 7;           // k half-step
    auto fillB = [&](int q, int s) {
        uint32_t* st = Bsm + s * BSTAGE;
        const int k0 = q * 32;
#pragma unroll
        for (int it = 0; it < 16; ++it) {
            const int j  = it * 2 + fjh;
            const int k  = k0 + j;
            const int ci = k / 3;
            const int kk3 = k - ci * 3;
            const int tg = t0 + ftt + kk3 - 1;
            float v = 0.0f;
            if (tg >= 0 && tg < T_LEN) v = __ldg(inb + (size_t)ci * T_LEN + tg);
            st[j * BPITCH + ftt] = f2tf(v);
        }
    };

    fillB(0, 0);
    __syncthreads();

    const uint4* Ap = reinterpret_cast<const uint4*>(wperm)
                    + ((size_t)cb * 48) * 32 * 32 + lane;

    for (int q = 0; q < KCHUNKS; ++q) {
        const int s = q & 1;
        if (q + 1 < KCHUNKS) fillB(q + 1, s ^ 1);

        const uint32_t* Bs = Bsm + s * BSTAGE;
        const uint4* Aq = Ap + (size_t)q * 32 * 32;
#pragma unroll
        for (int ks = 0; ks < 4; ++ks) {
            uint4 afr[4];
#pragma unroll
            for (int mt = 0; mt < 4; ++mt)
                afr[mt] = __ldg(Aq + (ks * 8 + wr * 4 + mt) * 32);
            uint2 bfr[4];
            const uint32_t* brow = Bs + (ks * 8 + (lane & 3)) * BPITCH
                                  + wc * 32 + (lane >> 2);
#pragma unroll
            for (int nt = 0; nt < 4; ++nt) {
                bfr[nt].x = brow[nt * 8];
                bfr[nt].y = brow[nt * 8 + 4 * BPITCH];
            }
#pragma unroll
            for (int mt = 0; mt < 4; ++mt)
#pragma unroll
                for (int nt = 0; nt < 4; ++nt)
                    mma_tf32(acc[mt][nt],
                             reinterpret_cast<const uint32_t*>(&afr[mt]),
                             reinterpret_cast<const uint32_t*>(&bfr[nt]));
        }
        __syncthreads();
    }

    // ---- epilogue ----
    const int gid = lane >> 2;
    const int tig = lane & 3;
#pragma unroll
    for (int mt = 0; mt < 4; ++mt) {
#pragma unroll
        for (int half = 0; half < 2; ++half) {
            const int co = co0 + wr * 64 + mt * 16 + gid + half * 8;
            const float bv = bias[co];
            float* orow = out + ((size_t)b * CCH + co) * T_LEN + t0 + wc * 32;
            const float* rrow = resid
                ? resid + ((size_t)b * CCH + co) * T_LEN + t0 + wc * 32 : nullptr;
#pragma unroll
            for (int nt = 0; nt < 4; ++nt) {
                const int n = nt * 8 + tig * 2;
                float lo = acc[mt][nt][half * 2 + 0] + bv;
                float hi = acc[mt][nt][half * 2 + 1] + bv;
                if (rrow) {
                    float2 rv = *reinterpret_cast<const float2*>(rrow + n);
                    lo += rv.x; hi += rv.y;
                }
                float2 v; v.x = lo; v.y = hi;
                *reinterpret_cast<float2*>(orow + n) = v;
            }
        }
    }
}

// ---------------------------------------------------------------------------
extern "C" void kernel_launch(void* const* d_in, const int* in_sizes, int n_in,
                              void* d_out, int out_size)
{
    const float* x    = (const float*)d_in[0];
    const float* a1a  = (const float*)d_in[1];
    const float* a1b  = (const float*)d_in[2];
    const float* a2a  = (const float*)d_in[3];
    const float* a2b  = (const float*)d_in[4];
    const float* c1w  = (const float*)d_in[5];
    const float* c1b  = (const float*)d_in[6];
    const float* c2w  = (const float*)d_in[7];
    const float* c2b  = (const float*)d_in[8];
    const float* fup  = (const float*)d_in[9];
    const float* fdn  = (const float*)d_in[10];
    float* out = (float*)d_out;

    float *g1, *g2;
    uint32_t *wp1, *wp2;
    cudaGetSymbolAddress((void**)&g1, g_buf1);
    cudaGetSymbolAddress((void**)&g2, g_buf2);
    cudaGetSymbolAddress((void**)&wp1, g_wperm1);
    cudaGetSymbolAddress((void**)&wp2, g_wperm2);

    dim3 gAct(T_LEN / 256, BATCH * CCH);
    dim3 gConv(T_LEN / 128, CCH / 128, BATCH);

    permute_w<<<768, 256>>>(c1w, wp1);
    permute_w<<<768, 256>>>(c2w, wp2);

    act_kernel<<<gAct, 256>>>(x, g1, a1a, a1b, fup, fdn);
    conv_tc<<<gConv, 256>>>(g1, wp1, c1b, nullptr, g2);
    act_kernel<<<gAct, 256>>>(g2, g1, a2a, a2b, fup, fdn);
    conv_tc<<<gConv, 256>>>(g1, wp2, c2b, x, out);
}

// round 6
// speedup vs baseline: 3.3945x; 1.2616x over previous
#include <cuda_runtime.h>
#include <cstdint>

#define T_LEN 8192
#define CCH   512
#define BATCH 8
#define NELEM (BATCH * CCH * T_LEN)

__device__ float g_buf1[NELEM];
__device__ float g_buf2[NELEM];

// Pre-permuted weights, mma-fragment order: [cb(4)][q(48)][frow(32)][lane(32)][4]
#define WPERM_U32 (4 * 48 * 32 * 32 * 4)
__device__ uint32_t g_wperm1[WPERM_U32];
__device__ uint32_t g_wperm2[WPERM_U32];

// ---------------------------------------------------------------------------
__device__ __forceinline__ uint32_t f2tf(float f) {
    uint32_t r;
    asm("cvt.rn.tf32.f32 %0, %1;" : "=r"(r) : "f"(f));
    return r;
}
__device__ __forceinline__ float f2tf_f(float f) {
    return __uint_as_float(f2tf(f));
}
__device__ __forceinline__ uint32_t smem_u32(const void* p) {
    uint32_t a;
    asm("{ .reg .u64 t; cvta.to.shared.u64 t, %1; cvt.u32.u64 %0, t; }"
        : "=r"(a) : "l"(p));
    return a;
}
__device__ __forceinline__ void cp_async4(uint32_t dst, const void* src, uint32_t srcsize) {
    asm volatile("cp.async.ca.shared.global [%0], [%1], 4, %2;"
                 :: "r"(dst), "l"(src), "r"(srcsize));
}
__device__ __forceinline__ void cp_commit() {
    asm volatile("cp.async.commit_group;" ::: "memory");
}
template <int N>
__device__ __forceinline__ void cp_wait() {
    asm volatile("cp.async.wait_group %0;" :: "n"(N) : "memory");
}
__device__ __forceinline__ void mma_tf32(float* d, const uint32_t* a, const uint32_t* b) {
    asm volatile(
        "mma.sync.aligned.m16n8k8.row.col.f32.tf32.tf32.f32 "
        "{%0,%1,%2,%3}, {%4,%5,%6,%7}, {%8,%9}, {%0,%1,%2,%3};"
        : "+f"(d[0]), "+f"(d[1]), "+f"(d[2]), "+f"(d[3])
        : "r"(a[0]), "r"(a[1]), "r"(a[2]), "r"(a[3]), "r"(b[0]), "r"(b[1]));
}

// ---------------------------------------------------------------------------
// Weight permutation (unchanged)
// ---------------------------------------------------------------------------
__global__ __launch_bounds__(256) void permute_w(
    const float* __restrict__ w, uint32_t* __restrict__ wp)
{
    const int tid = blockIdx.x * 256 + threadIdx.x;
    const int lane = tid & 31;
    const int frow = (tid >> 5) & 31;
    const int rest = tid >> 10;
    const int q  = rest % 48;
    const int cb = rest / 48;
    const int ks = frow >> 3;
    const int mt = frow & 7;

    uint4 v;
    uint32_t* o = &v.x;
#pragma unroll
    for (int rg = 0; rg < 4; ++rg) {
        const int m8 = (lane >> 2) + 8 * (rg & 1);
        const int kk = (lane & 3) + 4 * (rg >> 1);
        const int co = cb * 128 + mt * 16 + m8;
        const int k  = q * 32 + ks * 8 + kk;
        o[rg] = f2tf(w[(size_t)co * 1536 + k]);
    }
    reinterpret_cast<uint4*>(wp)[tid] = v;
}

// ---------------------------------------------------------------------------
// Act v2: 1024 outputs/block, 4 per thread. Output tf32-pre-rounded.
// ---------------------------------------------------------------------------
__global__ __launch_bounds__(256) void act_kernel(
    const float* __restrict__ in, float* __restrict__ out,
    const float* __restrict__ la, const float* __restrict__ lb,
    const float* __restrict__ fup, const float* __restrict__ fdn)
{
    __shared__ float sx[1040];
    __shared__ __align__(16) float sv[2064];
    __shared__ float su[12], sd[12];

    const int row = blockIdx.y;
    const int c   = row & (CCH - 1);
    const int t0  = blockIdx.x * 1024;
    const int tid = threadIdx.x;

    if (tid < 12) { su[tid] = fup[tid]; sd[tid] = fdn[tid]; }

    const float* xrow = in + (size_t)row * T_LEN;
#pragma unroll
    for (int it = 0; it < 5; ++it) {
        const int i = it * 256 + tid;
        if (i < 1040) {
            int g = t0 - 8 + i;
            g = min(max(g, 0), T_LEN - 1);
            sx[i] = xrow[g];
        }
    }
    __syncthreads();

    const float alpha = expf(la[c]);
    const float invb  = 1.0f / (expf(lb[c]) + 1e-9f);
    const int sx_off = 8 - t0;

    auto calc_sv = [&](int i) -> float {
        const int tp = 2 * t0 - 5 + i;
        float u;
        if (tp & 1) {
            const int h = (tp + 5) >> 1;
            const float* p = &sx[h + sx_off];
            u = su[0]*p[0] + su[2]*p[-1] + su[4]*p[-2]
              + su[6]*p[-3] + su[8]*p[-4] + su[10]*p[-5];
        } else {
            const int h = tp >> 1;
            const float* p = &sx[h + sx_off];
            u = su[1]*p[2] + su[3]*p[1] + su[5]*p[0]
              + su[7]*p[-1] + su[9]*p[-2] + su[11]*p[-3];
        }
        u *= 2.0f;
        const float s = __sinf(u * alpha);
        return u + s * s * invb;
    };

    {
        const int i0 = tid * 8;
        float v[8];
#pragma unroll
        for (int j = 0; j < 8; ++j) v[j] = calc_sv(i0 + j);
        float4 a, b;
        a.x = v[0]; a.y = v[1]; a.z = v[2]; a.w = v[3];
        b.x = v[4]; b.y = v[5]; b.z = v[6]; b.w = v[7];
        *reinterpret_cast<float4*>(&sv[i0])     = a;
        *reinterpret_cast<float4*>(&sv[i0 + 4]) = b;
        if (tid < 16) sv[2048 + tid] = calc_sv(2048 + tid);
    }
    __syncthreads();

    // Edge replication patches (reference clamps v index to [0, 2T-1]).
    if (t0 == 0 && tid < 5) sv[tid] = sv[5];                     // t' < 0 -> v[0]
    if (t0 == T_LEN - 1024 && tid < 11) sv[2053 + tid] = sv[2052]; // t' > 2T-1
    __syncthreads();

    // Downsample: 4 consecutive outputs/thread from register window v[0..17].
    {
        const float4 w0 = *reinterpret_cast<const float4*>(&sv[tid * 8]);
        const float4 w1 = *reinterpret_cast<const float4*>(&sv[tid * 8 + 4]);
        const float4 w2 = *reinterpret_cast<const float4*>(&sv[tid * 8 + 8]);
        const float4 w3 = *reinterpret_cast<const float4*>(&sv[tid * 8 + 12]);
        const float4 w4 = *reinterpret_cast<const float4*>(&sv[tid * 8 + 16]);
        float v[20];
        v[0]=w0.x; v[1]=w0.y; v[2]=w0.z; v[3]=w0.w;
        v[4]=w1.x; v[5]=w1.y; v[6]=w1.z; v[7]=w1.w;
        v[8]=w2.x; v[9]=w2.y; v[10]=w2.z; v[11]=w2.w;
        v[12]=w3.x; v[13]=w3.y; v[14]=w3.z; v[15]=w3.w;
        v[16]=w4.x; v[17]=w4.y; v[18]=w4.z; v[19]=w4.w;
        float z[4];
#pragma unroll
        for (int o = 0; o < 4; ++o) {
            float acc = 0.0f;
#pragma unroll
            for (int k = 0; k < 12; ++k) acc += sd[k] * v[2 * o + k];
            z[o] = f2tf_f(acc);   // pre-round for the tf32 conv consumer
        }
        float4 r; r.x = z[0]; r.y = z[1]; r.z = z[2]; r.w = z[3];
        *reinterpret_cast<float4*>(out + (size_t)row * T_LEN + t0 + tid * 4) = r;
    }
}

// ---------------------------------------------------------------------------
// tf32 HMMA implicit-GEMM conv. Block 128co x 128t, 4 warps (2x2), warp 64x64.
// A: fragment-order gmem LDG.128. B: im2col smem via cp.async (input is
// tf32-pre-rounded so no conversion needed), pitch 136 -> conflict-free LDS.
// ---------------------------------------------------------------------------
#define KCHUNKS 48
#define BPITCH 136
#define BSTAGE (32 * BPITCH)

template <int R0>
__device__ __forceinline__ void fillB_t(
    const float* __restrict__ inb, int ci_base, int t0, int tid,
    uint32_t dst0, bool lo_edge, bool hi_edge)
{
    const float* src0 = inb + (size_t)ci_base * T_LEN + t0 + tid - 1;
#pragma unroll
    for (int j = 0; j < 32; ++j) {
        constexpr_helper:;
        const int ciadd = (R0 + j) / 3;
        const int kk3   = (R0 + j) % 3;
        uint32_t ok = 4;
        if (kk3 == 0 && lo_edge) ok = 0;
        if (kk3 == 2 && hi_edge) ok = 0;
        cp_async4(dst0 + j * (BPITCH * 4),
                  src0 + (size_t)ciadd * T_LEN + kk3, ok);
    }
}

__global__ __launch_bounds__(128, 2)
void conv_tc(const float* __restrict__ in, const uint32_t* __restrict__ wperm,
             const float* __restrict__ bias, const float* __restrict__ resid,
             float* __restrict__ out)
{
    __shared__ uint32_t Bsm[2 * BSTAGE];

    const int tid  = threadIdx.x;
    const int wid  = tid >> 5;
    const int lane = tid & 31;
    const int wr   = wid >> 1;       // 0..1: M offset 64*wr
    const int wc   = wid & 1;        // 0..1: N offset 64*wc
    const int b    = blockIdx.z;
    const int cb   = blockIdx.y;
    const int co0  = cb * 128;
    const int t0   = blockIdx.x * 128;
    const float* inb = in + (size_t)b * CCH * T_LEN;

    const bool lo_edge = (t0 + tid == 0);
    const bool hi_edge = (t0 + tid == T_LEN - 1);

    float acc[4][8][4];
#pragma unroll
    for (int i = 0; i < 4; i++)
#pragma unroll
        for (int j = 0; j < 8; j++)
#pragma unroll
            for (int r = 0; r < 4; r++) acc[i][j][r] = 0.0f;

    const uint32_t smem0 = smem_u32(Bsm);

    auto fillB = [&](int q, int s) {
        const int k0 = q * 32;
        const int ci_base = k0 / 3;       // floor
        const int r0 = k0 - 3 * ci_base;  // (2q) % 3
        const uint32_t dst0 = smem0 + (s * BSTAGE + tid) * 4;
        if (r0 == 0)      fillB_t<0>(inb, ci_base, t0, tid, dst0, lo_edge, hi_edge);
        else if (r0 == 1) fillB_t<1>(inb, ci_base, t0, tid, dst0, lo_edge, hi_edge);
        else              fillB_t<2>(inb, ci_base, t0, tid, dst0, lo_edge, hi_edge);
        cp_commit();
    };

    fillB(0, 0);

    const uint4* Ap = reinterpret_cast<const uint4*>(wperm)
                    + ((size_t)cb * 48) * 32 * 32 + lane;

    for (int q = 0; q < KCHUNKS; ++q) {
        const int s = q & 1;
        if (q + 1 < KCHUNKS) {
            fillB(q + 1, s ^ 1);
            cp_wait<1>();
        } else {
            cp_wait<0>();
        }
        __syncthreads();

        const uint32_t* Bs = Bsm + s * BSTAGE;
        const uint4* Aq = Ap + (size_t)q * 1024;
#pragma unroll
        for (int ks = 0; ks < 4; ++ks) {
            uint4 afr[4];
#pragma unroll
            for (int mt = 0; mt < 4; ++mt)
                afr[mt] = __ldg(Aq + (ks * 8 + wr * 4 + mt) * 32);
            uint2 bfr[8];
            const uint32_t* brow = Bs + (ks * 8 + (lane & 3)) * BPITCH
                                  + wc * 64 + (lane >> 2);
#pragma unroll
            for (int nt = 0; nt < 8; ++nt) {
                bfr[nt].x = brow[nt * 8];
                bfr[nt].y = brow[nt * 8 + 4 * BPITCH];
            }
#pragma unroll
            for (int mt = 0; mt < 4; ++mt)
#pragma unroll
                for (int nt = 0; nt < 8; ++nt)
                    mma_tf32(acc[mt][nt],
                             reinterpret_cast<const uint32_t*>(&afr[mt]),
                             reinterpret_cast<const uint32_t*>(&bfr[nt]));
        }
        __syncthreads();
    }

    // ---- epilogue ----
    const int gid = lane >> 2;
    const int tig = lane & 3;
#pragma unroll
    for (int mt = 0; mt < 4; ++mt) {
#pragma unroll
        for (int half = 0; half < 2; ++half) {
            const int co = co0 + wr * 64 + mt * 16 + gid + half * 8;
            const float bv = __ldg(bias + co);
            float* orow = out + ((size_t)b * CCH + co) * T_LEN + t0 + wc * 64;
            const float* rrow = resid
                ? resid + ((size_t)b * CCH + co) * T_LEN + t0 + wc * 64 : nullptr;
#pragma unroll
            for (int nt = 0; nt < 8; ++nt) {
                const int n = nt * 8 + tig * 2;
                float lo = acc[mt][nt][half * 2 + 0] + bv;
                float hi = acc[mt][nt][half * 2 + 1] + bv;
                if (rrow) {
                    float2 rv = *reinterpret_cast<const float2*>(rrow + n);
                    lo += rv.x; hi += rv.y;
                }
                float2 v; v.x = lo; v.y = hi;
                *reinterpret_cast<float2*>(orow + n) = v;
            }
        }
    }
}

// ---------------------------------------------------------------------------
extern "C" void kernel_launch(void* const* d_in, const int* in_sizes, int n_in,
                              void* d_out, int out_size)
{
    const float* x    = (const float*)d_in[0];
    const float* a1a  = (const float*)d_in[1];
    const float* a1b  = (const float*)d_in[2];
    const float* a2a  = (const float*)d_in[3];
    const float* a2b  = (const float*)d_in[4];
    const float* c1w  = (const float*)d_in[5];
    const float* c1b  = (const float*)d_in[6];
    const float* c2w  = (const float*)d_in[7];
    const float* c2b  = (const float*)d_in[8];
    const float* fup  = (const float*)d_in[9];
    const float* fdn  = (const float*)d_in[10];
    float* out = (float*)d_out;

    float *g1, *g2;
    uint32_t *wp1, *wp2;
    cudaGetSymbolAddress((void**)&g1, g_buf1);
    cudaGetSymbolAddress((void**)&g2, g_buf2);
    cudaGetSymbolAddress((void**)&wp1, g_wperm1);
    cudaGetSymbolAddress((void**)&wp2, g_wperm2);

    dim3 gAct(T_LEN / 1024, BATCH * CCH);
    dim3 gConv(T_LEN / 128, CCH / 128, BATCH);

    permute_w<<<768, 256>>>(c1w, wp1);
    permute_w<<<768, 256>>>(c2w, wp2);

    act_kernel<<<gAct, 256>>>(x, g1, a1a, a1b, fup, fdn);
    conv_tc<<<gConv, 128>>>(g1, wp1, c1b, nullptr, g2);
    act_kernel<<<gAct, 256>>>(g2, g1, a2a, a2b, fup, fdn);
    conv_tc<<<gConv, 128>>>(g1, wp2, c2b, x, out);
}

// round 7
// speedup vs baseline: 3.9938x; 1.1765x over previous
#include <cuda_runtime.h>
#include <cstdint>

#define T_LEN 8192
#define CCH   512
#define BATCH 8
#define NELEM (BATCH * CCH * T_LEN)

__device__ float g_buf1[NELEM];
__device__ float g_buf2[NELEM];

// Pre-permuted weights, mma-fragment order: [cb(4)][q(48)][frow(32)][lane(32)][4]
#define WPERM_U32 (4 * 48 * 32 * 32 * 4)
__device__ uint32_t g_wperm1[WPERM_U32];
__device__ uint32_t g_wperm2[WPERM_U32];

// ---------------------------------------------------------------------------
__device__ __forceinline__ uint32_t f2tf(float f) {
    uint32_t r;
    asm("cvt.rn.tf32.f32 %0, %1;" : "=r"(r) : "f"(f));
    return r;
}
__device__ __forceinline__ float f2tf_f(float f) {
    return __uint_as_float(f2tf(f));
}
__device__ __forceinline__ uint32_t smem_u32(const void* p) {
    uint32_t a;
    asm("{ .reg .u64 t; cvta.to.shared.u64 t, %1; cvt.u32.u64 %0, t; }"
        : "=r"(a) : "l"(p));
    return a;
}
__device__ __forceinline__ void cp_async4(uint32_t dst, const void* src, uint32_t srcsize) {
    asm volatile("cp.async.ca.shared.global [%0], [%1], 4, %2;"
                 :: "r"(dst), "l"(src), "r"(srcsize));
}
__device__ __forceinline__ void cp_commit() {
    asm volatile("cp.async.commit_group;" ::: "memory");
}
template <int N>
__device__ __forceinline__ void cp_wait() {
    asm volatile("cp.async.wait_group %0;" :: "n"(N) : "memory");
}
__device__ __forceinline__ void mma_tf32(float* d, const uint32_t* a, const uint32_t* b) {
    asm volatile(
        "mma.sync.aligned.m16n8k8.row.col.f32.tf32.tf32.f32 "
        "{%0,%1,%2,%3}, {%4,%5,%6,%7}, {%8,%9}, {%0,%1,%2,%3};"
        : "+f"(d[0]), "+f"(d[1]), "+f"(d[2]), "+f"(d[3])
        : "r"(a[0]), "r"(a[1]), "r"(a[2]), "r"(a[3]), "r"(b[0]), "r"(b[1]));
}

// ---------------------------------------------------------------------------
// Weight permutation (unchanged)
// ---------------------------------------------------------------------------
__global__ __launch_bounds__(256) void permute_w(
    const float* __restrict__ w, uint32_t* __restrict__ wp)
{
    const int tid = blockIdx.x * 256 + threadIdx.x;
    const int lane = tid & 31;
    const int frow = (tid >> 5) & 31;
    const int rest = tid >> 10;
    const int q  = rest % 48;
    const int cb = rest / 48;
    const int ks = frow >> 3;
    const int mt = frow & 7;

    uint4 v;
    uint32_t* o = &v.x;
#pragma unroll
    for (int rg = 0; rg < 4; ++rg) {
        const int m8 = (lane >> 2) + 8 * (rg & 1);
        const int kk = (lane & 3) + 4 * (rg >> 1);
        const int co = cb * 128 + mt * 16 + m8;
        const int k  = q * 32 + ks * 8 + kk;
        o[rg] = f2tf(w[(size_t)co * 1536 + k]);
    }
    reinterpret_cast<uint4*>(wp)[tid] = v;
}

// ---------------------------------------------------------------------------
// Act v3: 1024 outputs/block, register-window upsample (3x LDS.128 per thread),
// smem sv only for the cross-thread downsample window. Output tf32-pre-rounded.
// ---------------------------------------------------------------------------
__global__ __launch_bounds__(256) void act_kernel(
    const float* __restrict__ in, float* __restrict__ out,
    const float* __restrict__ la, const float* __restrict__ lb,
    const float* __restrict__ fup, const float* __restrict__ fdn)
{
    __shared__ __align__(16) float sx[1040];
    __shared__ __align__(16) float sv[2064];
    __shared__ float su[12], sd[12];

    const int row = blockIdx.y;
    const int c   = row & (CCH - 1);
    const int t0  = blockIdx.x * 1024;
    const int tid = threadIdx.x;

    if (tid < 12) { su[tid] = fup[tid]; sd[tid] = fdn[tid]; }

    const float* xrow = in + (size_t)row * T_LEN;
#pragma unroll
    for (int it = 0; it < 5; ++it) {
        const int i = it * 256 + tid;
        if (i < 1040) {
            int g = t0 - 8 + i;
            g = min(max(g, 0), T_LEN - 1);
            sx[i] = xrow[g];
        }
    }
    __syncthreads();

    const float alpha = expf(la[c]);
    const float invb  = 1.0f / (expf(lb[c]) + 1e-9f);

    // filter taps to registers (broadcast LDS)
    float u0=su[0],u1=su[1],u2=su[2],u3=su[3],u4=su[4],u5=su[5],
          u6=su[6],u7=su[7],u8=su[8],u9=su[9],u10=su[10],u11=su[11];

    // ---- upsample + snake: 8 sv per thread from a 12-float register window ----
    {
        float xr[12];
        const float4 a0 = *reinterpret_cast<const float4*>(&sx[tid * 4]);
        const float4 a1 = *reinterpret_cast<const float4*>(&sx[tid * 4 + 4]);
        const float4 a2 = *reinterpret_cast<const float4*>(&sx[tid * 4 + 8]);
        xr[0]=a0.x; xr[1]=a0.y; xr[2]=a0.z; xr[3]=a0.w;
        xr[4]=a1.x; xr[5]=a1.y; xr[6]=a1.z; xr[7]=a1.w;
        xr[8]=a2.x; xr[9]=a2.y; xr[10]=a2.z; xr[11]=a2.w;

        float v[8];
#pragma unroll
        for (int m = 0; m < 4; ++m) {
            // i = 2m: odd t' tap set (su even indices); i = 2m+1: even t' taps.
            float ua = u0*xr[8+m] + u2*xr[7+m] + u4*xr[6+m]
                     + u6*xr[5+m] + u8*xr[4+m] + u10*xr[3+m];
            float ub = u1*xr[8+m] + u3*xr[7+m] + u5*xr[6+m]
                     + u7*xr[5+m] + u9*xr[4+m] + u11*xr[3+m];
            ua *= 2.0f; ub *= 2.0f;
            const float sa = __sinf(ua * alpha);
            const float sb = __sinf(ub * alpha);
            v[2*m]   = ua + sa * sa * invb;
            v[2*m+1] = ub + sb * sb * invb;
        }
        float4 o0, o1;
        o0.x=v[0]; o0.y=v[1]; o0.z=v[2]; o0.w=v[3];
        o1.x=v[4]; o1.y=v[5]; o1.z=v[6]; o1.w=v[7];
        *reinterpret_cast<float4*>(&sv[tid * 8])     = o0;
        *reinterpret_cast<float4*>(&sv[tid * 8 + 4]) = o1;
    }
    // tail sv[2048..2063]
    if (tid < 16) {
        const int i = 2048 + tid;
        const int tp = 2 * t0 - 5 + i;
        const int sx_off = 8 - t0;
        float u;
        if (tp & 1) {
            const int h = (tp + 5) >> 1;
            const float* p = &sx[h + sx_off];
            u = u0*p[0] + u2*p[-1] + u4*p[-2] + u6*p[-3] + u8*p[-4] + u10*p[-5];
        } else {
            const int h = tp >> 1;
            const float* p = &sx[h + sx_off];
            u = u1*p[2] + u3*p[1] + u5*p[0] + u7*p[-1] + u9*p[-2] + u11*p[-3];
        }
        u *= 2.0f;
        const float s = __sinf(u * alpha);
        sv[i] = u + s * s * invb;
    }
    __syncthreads();

    // edge replication (reference clamps v index to [0, 2T-1])
    if (t0 == 0 && tid < 5) sv[tid] = sv[5];
    if (t0 == T_LEN - 1024 && tid < 11) sv[2053 + tid] = sv[2052];
    __syncthreads();

    // ---- downsample: 4 outputs/thread ----
    {
        float d0=sd[0],d1=sd[1],d2=sd[2],d3=sd[3],d4=sd[4],d5=sd[5],
              d6=sd[6],d7=sd[7],d8=sd[8],d9=sd[9],d10=sd[10],d11=sd[11];
        const float4 w0 = *reinterpret_cast<const float4*>(&sv[tid * 8]);
        const float4 w1 = *reinterpret_cast<const float4*>(&sv[tid * 8 + 4]);
        const float4 w2 = *reinterpret_cast<const float4*>(&sv[tid * 8 + 8]);
        const float4 w3 = *reinterpret_cast<const float4*>(&sv[tid * 8 + 12]);
        const float4 w4 = *reinterpret_cast<const float4*>(&sv[tid * 8 + 16]);
        float v[20];
        v[0]=w0.x; v[1]=w0.y; v[2]=w0.z; v[3]=w0.w;
        v[4]=w1.x; v[5]=w1.y; v[6]=w1.z; v[7]=w1.w;
        v[8]=w2.x; v[9]=w2.y; v[10]=w2.z; v[11]=w2.w;
        v[12]=w3.x; v[13]=w3.y; v[14]=w3.z; v[15]=w3.w;
        v[16]=w4.x; v[17]=w4.y; v[18]=w4.z; v[19]=w4.w;
        float z[4];
#pragma unroll
        for (int o = 0; o < 4; ++o) {
            const float* p = v + 2 * o;
            float acc = d0*p[0] + d1*p[1] + d2*p[2] + d3*p[3] + d4*p[4] + d5*p[5]
                      + d6*p[6] + d7*p[7] + d8*p[8] + d9*p[9] + d10*p[10] + d11*p[11];
            z[o] = f2tf_f(acc);
        }
        float4 r; r.x = z[0]; r.y = z[1]; r.z = z[2]; r.w = z[3];
        *reinterpret_cast<float4*>(out + (size_t)row * T_LEN + t0 + tid * 4) = r;
    }
}

// ---------------------------------------------------------------------------
// tf32 HMMA implicit-GEMM conv. Block 128co x 128t, 4 warps (2x2), warp 64x64.
// 64-k double-buffered stages (24 iterations) to halve sync bubbles.
// A: fragment-order gmem LDG.128. B: [k(64)][t(128)] smem, pitch 136.
// ---------------------------------------------------------------------------
#define NSTAGES_K 24
#define BPITCH 136
#define BSTAGE (64 * BPITCH)               // 8704 words
#define CONV_SMEM (2 * BSTAGE * 4)         // 69632 B

template <int R0>
__device__ __forceinline__ void fillB_t(
    const float* __restrict__ inb, int ci_base, int t0, int tid,
    uint32_t dst0, bool lo_edge, bool hi_edge)
{
    const float* src0 = inb + (size_t)ci_base * T_LEN + t0 + tid - 1;
#pragma unroll
    for (int j = 0; j < 64; ++j) {
        const int ciadd = (R0 + j) / 3;
        const int kk3   = (R0 + j) % 3;
        uint32_t ok = 4;
        if (kk3 == 0 && lo_edge) ok = 0;
        if (kk3 == 2 && hi_edge) ok = 0;
        cp_async4(dst0 + j * (BPITCH * 4),
                  src0 + (size_t)ciadd * T_LEN + kk3, ok);
    }
}

__global__ __launch_bounds__(128, 2)
void conv_tc(const float* __restrict__ in, const uint32_t* __restrict__ wperm,
             const float* __restrict__ bias, const float* __restrict__ resid,
             float* __restrict__ out)
{
    extern __shared__ uint32_t Bsm[];

    const int tid  = threadIdx.x;
    const int wid  = tid >> 5;
    const int lane = tid & 31;
    const int wr   = wid >> 1;
    const int wc   = wid & 1;
    const int b    = blockIdx.z;
    const int cb   = blockIdx.y;
    const int co0  = cb * 128;
    const int t0   = blockIdx.x * 128;
    const float* inb = in + (size_t)b * CCH * T_LEN;

    const bool lo_edge = (t0 + tid == 0);
    const bool hi_edge = (t0 + tid == T_LEN - 1);

    float acc[4][8][4];
#pragma unroll
    for (int i = 0; i < 4; i++)
#pragma unroll
        for (int j = 0; j < 8; j++)
#pragma unroll
            for (int r = 0; r < 4; r++) acc[i][j][r] = 0.0f;

    const uint32_t smem0 = smem_u32(Bsm);

    auto fillB = [&](int q, int s) {
        const int k0 = q * 64;
        const int ci_base = k0 / 3;
        const int r0 = k0 - 3 * ci_base;     // = q % 3
        const uint32_t dst0 = smem0 + (s * BSTAGE + tid) * 4;
        if (r0 == 0)      fillB_t<0>(inb, ci_base, t0, tid, dst0, lo_edge, hi_edge);
        else if (r0 == 1) fillB_t<1>(inb, ci_base, t0, tid, dst0, lo_edge, hi_edge);
        else              fillB_t<2>(inb, ci_base, t0, tid, dst0, lo_edge, hi_edge);
        cp_commit();
    };

    fillB(0, 0);

    const uint4* Ap = reinterpret_cast<const uint4*>(wperm)
                    + ((size_t)cb * 48) * 32 * 32 + lane;

    for (int q = 0; q < NSTAGES_K; ++q) {
        const int s = q & 1;
        if (q + 1 < NSTAGES_K) {
            fillB(q + 1, s ^ 1);
            cp_wait<1>();
        } else {
            cp_wait<0>();
        }
        __syncthreads();

        const uint32_t* Bs = Bsm + s * BSTAGE;
        const uint4* Aq = Ap + (size_t)q * 2048;
#pragma unroll
        for (int ks = 0; ks < 8; ++ks) {
            uint4 afr[4];
#pragma unroll
            for (int mt = 0; mt < 4; ++mt)
                afr[mt] = __ldg(Aq + (ks * 8 + wr * 4 + mt) * 32);
            uint2 bfr[8];
            const uint32_t* brow = Bs + (ks * 8 + (lane & 3)) * BPITCH
                                  + wc * 64 + (lane >> 2);
#pragma unroll
            for (int nt = 0; nt < 8; ++nt) {
                bfr[nt].x = brow[nt * 8];
                bfr[nt].y = brow[nt * 8 + 4 * BPITCH];
            }
#pragma unroll
            for (int mt = 0; mt < 4; ++mt)
#pragma unroll
                for (int nt = 0; nt < 8; ++nt)
                    mma_tf32(acc[mt][nt],
                             reinterpret_cast<const uint32_t*>(&afr[mt]),
                             reinterpret_cast<const uint32_t*>(&bfr[nt]));
        }
        __syncthreads();
    }

    // ---- epilogue ----
    const int gid = lane >> 2;
    const int tig = lane & 3;
#pragma unroll
    for (int mt = 0; mt < 4; ++mt) {
#pragma unroll
        for (int half = 0; half < 2; ++half) {
            const int co = co0 + wr * 64 + mt * 16 + gid + half * 8;
            const float bv = __ldg(bias + co);
            float* orow = out + ((size_t)b * CCH + co) * T_LEN + t0 + wc * 64;
            const float* rrow = resid
                ? resid + ((size_t)b * CCH + co) * T_LEN + t0 + wc * 64 : nullptr;
#pragma unroll
            for (int nt = 0; nt < 8; ++nt) {
                const int n = nt * 8 + tig * 2;
                float lo = acc[mt][nt][half * 2 + 0] + bv;
                float hi = acc[mt][nt][half * 2 + 1] + bv;
                if (rrow) {
                    float2 rv = *reinterpret_cast<const float2*>(rrow + n);
                    lo += rv.x; hi += rv.y;
                }
                float2 v; v.x = lo; v.y = hi;
                *reinterpret_cast<float2*>(orow + n) = v;
            }
        }
    }
}

// ---------------------------------------------------------------------------
extern "C" void kernel_launch(void* const* d_in, const int* in_sizes, int n_in,
                              void* d_out, int out_size)
{
    const float* x    = (const float*)d_in[0];
    const float* a1a  = (const float*)d_in[1];
    const float* a1b  = (const float*)d_in[2];
    const float* a2a  = (const float*)d_in[3];
    const float* a2b  = (const float*)d_in[4];
    const float* c1w  = (const float*)d_in[5];
    const float* c1b  = (const float*)d_in[6];
    const float* c2w  = (const float*)d_in[7];
    const float* c2b  = (const float*)d_in[8];
    const float* fup  = (const float*)d_in[9];
    const float* fdn  = (const float*)d_in[10];
    float* out = (float*)d_out;

    float *g1, *g2;
    uint32_t *wp1, *wp2;
    cudaGetSymbolAddress((void**)&g1, g_buf1);
    cudaGetSymbolAddress((void**)&g2, g_buf2);
    cudaGetSymbolAddress((void**)&wp1, g_wperm1);
    cudaGetSymbolAddress((void**)&wp2, g_wperm2);

    cudaFuncSetAttribute(conv_tc, cudaFuncAttributeMaxDynamicSharedMemorySize, CONV_SMEM);

    dim3 gAct(T_LEN / 1024, BATCH * CCH);
    dim3 gConv(T_LEN / 128, CCH / 128, BATCH);

    permute_w<<<768, 256>>>(c1w, wp1);
    permute_w<<<768, 256>>>(c2w, wp2);

    act_kernel<<<gAct, 256>>>(x, g1, a1a, a1b, fup, fdn);
    conv_tc<<<gConv, 128, CONV_SMEM>>>(g1, wp1, c1b, nullptr, g2);
    act_kernel<<<gAct, 256>>>(g2, g1, a2a, a2b, fup, fdn);
    conv_tc<<<gConv, 128, CONV_SMEM>>>(g1, wp2, c2b, x, out);
}

// round 8
// speedup vs baseline: 4.2018x; 1.0521x over previous
#include <cuda_runtime.h>
#include <cstdint>

#define T_LEN 8192
#define CCH   512
#define BATCH 8
#define NELEM (BATCH * CCH * T_LEN)

__device__ float g_buf1[NELEM];
__device__ float g_buf2[NELEM];

// Pre-permuted weights, mma-fragment order: [cb(4)][q(48)][frow(32)][lane(32)][4]
#define WPERM_U32 (4 * 48 * 32 * 32 * 4)
__device__ uint32_t g_wperm1[WPERM_U32];
__device__ uint32_t g_wperm2[WPERM_U32];

// ---------------------------------------------------------------------------
__device__ __forceinline__ uint32_t f2tf(float f) {
    uint32_t r;
    asm("cvt.rn.tf32.f32 %0, %1;" : "=r"(r) : "f"(f));
    return r;
}
__device__ __forceinline__ float f2tf_f(float f) {
    return __uint_as_float(f2tf(f));
}
__device__ __forceinline__ uint32_t smem_u32(const void* p) {
    uint32_t a;
    asm("{ .reg .u64 t; cvta.to.shared.u64 t, %1; cvt.u32.u64 %0, t; }"
        : "=r"(a) : "l"(p));
    return a;
}
__device__ __forceinline__ void cp_async4(uint32_t dst, const void* src, uint32_t srcsize) {
    asm volatile("cp.async.ca.shared.global [%0], [%1], 4, %2;"
                 :: "r"(dst), "l"(src), "r"(srcsize));
}
__device__ __forceinline__ void cp_async16(uint32_t dst, const void* src) {
    asm volatile("cp.async.cg.shared.global [%0], [%1], 16;"
                 :: "r"(dst), "l"(src));
}
__device__ __forceinline__ void cp_commit() {
    asm volatile("cp.async.commit_group;" ::: "memory");
}
template <int N>
__device__ __forceinline__ void cp_wait() {
    asm volatile("cp.async.wait_group %0;" :: "n"(N) : "memory");
}
__device__ __forceinline__ void mma_tf32(float* d, const uint32_t* a, const uint32_t* b) {
    asm volatile(
        "mma.sync.aligned.m16n8k8.row.col.f32.tf32.tf32.f32 "
        "{%0,%1,%2,%3}, {%4,%5,%6,%7}, {%8,%9}, {%0,%1,%2,%3};"
        : "+f"(d[0]), "+f"(d[1]), "+f"(d[2]), "+f"(d[3])
        : "r"(a[0]), "r"(a[1]), "r"(a[2]), "r"(a[3]), "r"(b[0]), "r"(b[1]));
}

// ---------------------------------------------------------------------------
// Weight permutation (unchanged)
// ---------------------------------------------------------------------------
__global__ __launch_bounds__(256) void permute_w(
    const float* __restrict__ w, uint32_t* __restrict__ wp)
{
    const int tid = blockIdx.x * 256 + threadIdx.x;
    const int lane = tid & 31;
    const int frow = (tid >> 5) & 31;
    const int rest = tid >> 10;
    const int q  = rest % 48;
    const int cb = rest / 48;
    const int ks = frow >> 3;
    const int mt = frow & 7;

    uint4 v;
    uint32_t* o = &v.x;
#pragma unroll
    for (int rg = 0; rg < 4; ++rg) {
        const int m8 = (lane >> 2) + 8 * (rg & 1);
        const int kk = (lane & 3) + 4 * (rg >> 1);
        const int co = cb * 128 + mt * 16 + m8;
        const int k  = q * 32 + ks * 8 + kk;
        o[rg] = f2tf(w[(size_t)co * 1536 + k]);
    }
    reinterpret_cast<uint4*>(wp)[tid] = v;
}

// ---------------------------------------------------------------------------
// Act v3 (unchanged from round 7)
// ---------------------------------------------------------------------------
__global__ __launch_bounds__(256) void act_kernel(
    const float* __restrict__ in, float* __restrict__ out,
    const float* __restrict__ la, const float* __restrict__ lb,
    const float* __restrict__ fup, const float* __restrict__ fdn)
{
    __shared__ __align__(16) float sx[1040];
    __shared__ __align__(16) float sv[2064];
    __shared__ float su[12], sd[12];

    const int row = blockIdx.y;
    const int c   = row & (CCH - 1);
    const int t0  = blockIdx.x * 1024;
    const int tid = threadIdx.x;

    if (tid < 12) { su[tid] = fup[tid]; sd[tid] = fdn[tid]; }

    const float* xrow = in + (size_t)row * T_LEN;
#pragma unroll
    for (int it = 0; it < 5; ++it) {
        const int i = it * 256 + tid;
        if (i < 1040) {
            int g = t0 - 8 + i;
            g = min(max(g, 0), T_LEN - 1);
            sx[i] = xrow[g];
        }
    }
    __syncthreads();

    const float alpha = expf(la[c]);
    const float invb  = 1.0f / (expf(lb[c]) + 1e-9f);

    float u0=su[0],u1=su[1],u2=su[2],u3=su[3],u4=su[4],u5=su[5],
          u6=su[6],u7=su[7],u8=su[8],u9=su[9],u10=su[10],u11=su[11];

    {
        float xr[12];
        const float4 a0 = *reinterpret_cast<const float4*>(&sx[tid * 4]);
        const float4 a1 = *reinterpret_cast<const float4*>(&sx[tid * 4 + 4]);
        const float4 a2 = *reinterpret_cast<const float4*>(&sx[tid * 4 + 8]);
        xr[0]=a0.x; xr[1]=a0.y; xr[2]=a0.z; xr[3]=a0.w;
        xr[4]=a1.x; xr[5]=a1.y; xr[6]=a1.z; xr[7]=a1.w;
        xr[8]=a2.x; xr[9]=a2.y; xr[10]=a2.z; xr[11]=a2.w;

        float v[8];
#pragma unroll
        for (int m = 0; m < 4; ++m) {
            float ua = u0*xr[8+m] + u2*xr[7+m] + u4*xr[6+m]
                     + u6*xr[5+m] + u8*xr[4+m] + u10*xr[3+m];
            float ub = u1*xr[8+m] + u3*xr[7+m] + u5*xr[6+m]
                     + u7*xr[5+m] + u9*xr[4+m] + u11*xr[3+m];
            ua *= 2.0f; ub *= 2.0f;
            const float sa = __sinf(ua * alpha);
            const float sb = __sinf(ub * alpha);
            v[2*m]   = ua + sa * sa * invb;
            v[2*m+1] = ub + sb * sb * invb;
        }
        float4 o0, o1;
        o0.x=v[0]; o0.y=v[1]; o0.z=v[2]; o0.w=v[3];
        o1.x=v[4]; o1.y=v[5]; o1.z=v[6]; o1.w=v[7];
        *reinterpret_cast<float4*>(&sv[tid * 8])     = o0;
        *reinterpret_cast<float4*>(&sv[tid * 8 + 4]) = o1;
    }
    if (tid < 16) {
        const int i = 2048 + tid;
        const int tp = 2 * t0 - 5 + i;
        const int sx_off = 8 - t0;
        float u;
        if (tp & 1) {
            const int h = (tp + 5) >> 1;
            const float* p = &sx[h + sx_off];
            u = u0*p[0] + u2*p[-1] + u4*p[-2] + u6*p[-3] + u8*p[-4] + u10*p[-5];
        } else {
            const int h = tp >> 1;
            const float* p = &sx[h + sx_off];
            u = u1*p[2] + u3*p[1] + u5*p[0] + u7*p[-1] + u9*p[-2] + u11*p[-3];
        }
        u *= 2.0f;
        const float s = __sinf(u * alpha);
        sv[i] = u + s * s * invb;
    }
    __syncthreads();

    if (t0 == 0 && tid < 5) sv[tid] = sv[5];
    if (t0 == T_LEN - 1024 && tid < 11) sv[2053 + tid] = sv[2052];
    __syncthreads();

    {
        float d0=sd[0],d1=sd[1],d2=sd[2],d3=sd[3],d4=sd[4],d5=sd[5],
              d6=sd[6],d7=sd[7],d8=sd[8],d9=sd[9],d10=sd[10],d11=sd[11];
        const float4 w0 = *reinterpret_cast<const float4*>(&sv[tid * 8]);
        const float4 w1 = *reinterpret_cast<const float4*>(&sv[tid * 8 + 4]);
        const float4 w2 = *reinterpret_cast<const float4*>(&sv[tid * 8 + 8]);
        const float4 w3 = *reinterpret_cast<const float4*>(&sv[tid * 8 + 12]);
        const float4 w4 = *reinterpret_cast<const float4*>(&sv[tid * 8 + 16]);
        float v[20];
        v[0]=w0.x; v[1]=w0.y; v[2]=w0.z; v[3]=w0.w;
        v[4]=w1.x; v[5]=w1.y; v[6]=w1.z; v[7]=w1.w;
        v[8]=w2.x; v[9]=w2.y; v[10]=w2.z; v[11]=w2.w;
        v[12]=w3.x; v[13]=w3.y; v[14]=w3.z; v[15]=w3.w;
        v[16]=w4.x; v[17]=w4.y; v[18]=w4.z; v[19]=w4.w;
        float z[4];
#pragma unroll
        for (int o = 0; o < 4; ++o) {
            const float* p = v + 2 * o;
            float acc = d0*p[0] + d1*p[1] + d2*p[2] + d3*p[3] + d4*p[4] + d5*p[5]
                      + d6*p[6] + d7*p[7] + d8*p[8] + d9*p[9] + d10*p[10] + d11*p[11];
            z[o] = f2tf_f(acc);
        }
        float4 r; r.x = z[0]; r.y = z[1]; r.z = z[2]; r.w = z[3];
        *reinterpret_cast<float4*>(out + (size_t)row * T_LEN + t0 + tid * 4) = r;
    }
}

// ---------------------------------------------------------------------------
// tf32 HMMA implicit-GEMM conv. Block 128co x 128t, 4 warps (2x2), warp 64x64.
// 32-k double-buffered stages; BOTH A and B staged in smem via cp.async so all
// consumer loads are 29-cyc LDS. One __syncthreads per stage.
// Stage: A 4096 words (frag order) + B 32x136 words.  2 stages = 66KB.
// ---------------------------------------------------------------------------
#define KCHUNKS 48
#define BPITCH 136
#define ASTAGE_W 4096
#define BSTAGE_W (32 * BPITCH)
#define STAGE_W  (ASTAGE_W + BSTAGE_W)      // 8448 words
#define CONV_SMEM (2 * STAGE_W * 4)         // 67584 B

template <int R0>
__device__ __forceinline__ void fillB_t(
    const float* __restrict__ inb, int ci_base, int t0, int tid,
    uint32_t dst0, bool lo_edge, bool hi_edge)
{
    const float* src0 = inb + (size_t)ci_base * T_LEN + t0 + tid - 1;
#pragma unroll
    for (int j = 0; j < 32; ++j) {
        const int ciadd = (R0 + j) / 3;
        const int kk3   = (R0 + j) % 3;
        uint32_t ok = 4;
        if (kk3 == 0 && lo_edge) ok = 0;
        if (kk3 == 2 && hi_edge) ok = 0;
        cp_async4(dst0 + j * (BPITCH * 4),
                  src0 + (size_t)ciadd * T_LEN + kk3, ok);
    }
}

__global__ __launch_bounds__(128, 2)
void conv_tc(const float* __restrict__ in, const uint32_t* __restrict__ wperm,
             const float* __restrict__ bias, const float* __restrict__ resid,
             float* __restrict__ out)
{
    extern __shared__ uint32_t Ssm[];

    const int tid  = threadIdx.x;
    const int wid  = tid >> 5;
    const int lane = tid & 31;
    const int wr   = wid >> 1;
    const int wc   = wid & 1;
    const int b    = blockIdx.z;
    const int cb   = blockIdx.y;
    const int co0  = cb * 128;
    const int t0   = blockIdx.x * 128;
    const float* inb = in + (size_t)b * CCH * T_LEN;

    const bool lo_edge = (t0 + tid == 0);
    const bool hi_edge = (t0 + tid == T_LEN - 1);

    float acc[4][8][4];
#pragma unroll
    for (int i = 0; i < 4; i++)
#pragma unroll
        for (int j = 0; j < 8; j++)
#pragma unroll
            for (int r = 0; r < 4; r++) acc[i][j][r] = 0.0f;

    const uint32_t smem0 = smem_u32(Ssm);

    auto fill = [&](int q, int s) {
        // A: 1024 uint4 per stage, 8 cp.async.16 per thread
        const uint4* Asrc = reinterpret_cast<const uint4*>(wperm)
                          + ((size_t)(cb * 48 + q)) * 1024 + tid;
        const uint32_t dstA = smem0 + s * (STAGE_W * 4) + tid * 16;
#pragma unroll
        for (int it = 0; it < 8; ++it)
            cp_async16(dstA + it * 2048, Asrc + it * 128);
        // B: im2col rows
        const int k0 = q * 32;
        const int ci_base = k0 / 3;
        const int r0 = k0 - 3 * ci_base;   // (2q)%3
        const uint32_t dstB = smem0 + (s * STAGE_W + ASTAGE_W + tid) * 4;
        if (r0 == 0)      fillB_t<0>(inb, ci_base, t0, tid, dstB, lo_edge, hi_edge);
        else if (r0 == 1) fillB_t<1>(inb, ci_base, t0, tid, dstB, lo_edge, hi_edge);
        else              fillB_t<2>(inb, ci_base, t0, tid, dstB, lo_edge, hi_edge);
        cp_commit();
    };

    fill(0, 0);

    for (int q = 0; q < KCHUNKS; ++q) {
        const int s = q & 1;
        cp_wait<0>();
        __syncthreads();
        if (q + 1 < KCHUNKS) fill(q + 1, s ^ 1);

        const uint32_t* As = Ssm + s * STAGE_W;
        const uint32_t* Bs = As + ASTAGE_W;
#pragma unroll
        for (int ks = 0; ks < 4; ++ks) {
            uint4 afr[4];
#pragma unroll
            for (int mt = 0; mt < 4; ++mt)
                afr[mt] = *reinterpret_cast<const uint4*>(
                    As + ((ks * 8 + wr * 4 + mt) * 32 + lane) * 4);
            uint2 bfr[8];
            const uint32_t* brow = Bs + (ks * 8 + (lane & 3)) * BPITCH
                                  + wc * 64 + (lane >> 2);
#pragma unroll
            for (int nt = 0; nt < 8; ++nt) {
                bfr[nt].x = brow[nt * 8];
                bfr[nt].y = brow[nt * 8 + 4 * BPITCH];
            }
#pragma unroll
            for (int mt = 0; mt < 4; ++mt)
#pragma unroll
                for (int nt = 0; nt < 8; ++nt)
                    mma_tf32(acc[mt][nt],
                             reinterpret_cast<const uint32_t*>(&afr[mt]),
                             reinterpret_cast<const uint32_t*>(&bfr[nt]));
        }
    }

    __syncthreads();

    // ---- epilogue ----
    const int gid = lane >> 2;
    const int tig = lane & 3;
#pragma unroll
    for (int mt = 0; mt < 4; ++mt) {
#pragma unroll
        for (int half = 0; half < 2; ++half) {
            const int co = co0 + wr * 64 + mt * 16 + gid + half * 8;
            const float bv = __ldg(bias + co);
            float* orow = out + ((size_t)b * CCH + co) * T_LEN + t0 + wc * 64;
            const float* rrow = resid
                ? resid + ((size_t)b * CCH + co) * T_LEN + t0 + wc * 64 : nullptr;
#pragma unroll
            for (int nt = 0; nt < 8; ++nt) {
                const int n = nt * 8 + tig * 2;
                float lo = acc[mt][nt][half * 2 + 0] + bv;
                float hi = acc[mt][nt][half * 2 + 1] + bv;
                if (rrow) {
                    float2 rv = *reinterpret_cast<const float2*>(rrow + n);
                    lo += rv.x; hi += rv.y;
                }
                float2 v; v.x = lo; v.y = hi;
                *reinterpret_cast<float2*>(orow + n) = v;
            }
        }
    }
}

// ---------------------------------------------------------------------------
extern "C" void kernel_launch(void* const* d_in, const int* in_sizes, int n_in,
                              void* d_out, int out_size)
{
    const float* x    = (const float*)d_in[0];
    const float* a1a  = (const float*)d_in[1];
    const float* a1b  = (const float*)d_in[2];
    const float* a2a  = (const float*)d_in[3];
    const float* a2b  = (const float*)d_in[4];
    const float* c1w  = (const float*)d_in[5];
    const float* c1b  = (const float*)d_in[6];
    const float* c2w  = (const float*)d_in[7];
    const float* c2b  = (const float*)d_in[8];
    const float* fup  = (const float*)d_in[9];
    const float* fdn  = (const float*)d_in[10];
    float* out = (float*)d_out;

    float *g1, *g2;
    uint32_t *wp1, *wp2;
    cudaGetSymbolAddress((void**)&g1, g_buf1);
    cudaGetSymbolAddress((void**)&g2, g_buf2);
    cudaGetSymbolAddress((void**)&wp1, g_wperm1);
    cudaGetSymbolAddress((void**)&wp2, g_wperm2);

    cudaFuncSetAttribute(conv_tc, cudaFuncAttributeMaxDynamicSharedMemorySize, CONV_SMEM);

    dim3 gAct(T_LEN / 1024, BATCH * CCH);
    dim3 gConv(T_LEN / 128, CCH / 128, BATCH);

    permute_w<<<768, 256>>>(c1w, wp1);
    permute_w<<<768, 256>>>(c2w, wp2);

    act_kernel<<<gAct, 256>>>(x, g1, a1a, a1b, fup, fdn);
    conv_tc<<<gConv, 128, CONV_SMEM>>>(g1, wp1, c1b, nullptr, g2);
    act_kernel<<<gAct, 256>>>(g2, g1, a2a, a2b, fup, fdn);
    conv_tc<<<gConv, 128, CONV_SMEM>>>(g1, wp2, c2b, x, out);
}

// round 9
// speedup vs baseline: 5.3513x; 1.2736x over previous
#include <cuda_runtime.h>
#include <cstdint>

#define T_LEN 8192
#define CCH   512
#define BATCH 8
#define NELEM (BATCH * CCH * T_LEN)

__device__ float g_buf1[NELEM];
__device__ float g_buf2[NELEM];

// Pre-permuted f16 weights, mma-fragment order:
// [cb(4)][q(48)][frow(16)][lane(32)] x uint4 (4 f16x2 regs)
#define WPERM_U32 (4 * 48 * 16 * 32 * 4)   // 393216 words
__device__ uint32_t g_wperm1[WPERM_U32];
__device__ uint32_t g_wperm2[WPERM_U32];

// ---------------------------------------------------------------------------
__device__ __forceinline__ uint32_t smem_u32(const void* p) {
    uint32_t a;
    asm("{ .reg .u64 t; cvta.to.shared.u64 t, %1; cvt.u32.u64 %0, t; }"
        : "=r"(a) : "l"(p));
    return a;
}
__device__ __forceinline__ void sts32(uint32_t addr, uint32_t v) {
    asm volatile("st.shared.b32 [%0], %1;" :: "r"(addr), "r"(v));
}
__device__ __forceinline__ uint32_t pack_f16x2(float lo, float hi) {
    uint32_t r;
    asm("cvt.rn.f16x2.f32 %0, %1, %2;" : "=r"(r) : "f"(hi), "f"(lo));
    return r;
}
__device__ __forceinline__ void cp_async16(uint32_t dst, const void* src) {
    asm volatile("cp.async.cg.shared.global [%0], [%1], 16;"
                 :: "r"(dst), "l"(src));
}
__device__ __forceinline__ void cp_commit() {
    asm volatile("cp.async.commit_group;" ::: "memory");
}
template <int N>
__device__ __forceinline__ void cp_wait() {
    asm volatile("cp.async.wait_group %0;" :: "n"(N) : "memory");
}
// m16n8k16 fp16 mma, fp32 accumulate (sm_80+ universal PTX)
__device__ __forceinline__ void mma_f16(float* d, const uint32_t* a, const uint32_t* b) {
    asm volatile(
        "mma.sync.aligned.m16n8k16.row.col.f32.f16.f16.f32 "
        "{%0,%1,%2,%3}, {%4,%5,%6,%7}, {%8,%9}, {%0,%1,%2,%3};"
        : "+f"(d[0]), "+f"(d[1]), "+f"(d[2]), "+f"(d[3])
        : "r"(a[0]), "r"(a[1]), "r"(a[2]), "r"(a[3]), "r"(b[0]), "r"(b[1]));
}

// ---------------------------------------------------------------------------
// Weight permutation -> f16x2 fragments.
// frag reg rg: row = (lane>>2) + 8*(rg&1); k = base + 2*(lane&3) + 8*(rg>>1) + {0,1}
// ---------------------------------------------------------------------------
__global__ __launch_bounds__(256) void permute_w(
    const float* __restrict__ w, uint32_t* __restrict__ wp)
{
    const int tid = blockIdx.x * 256 + threadIdx.x;    // 0..98303
    const int lane = tid & 31;
    const int frow = (tid >> 5) & 15;
    const int rest = tid >> 9;
    const int q  = rest % 48;
    const int cb = rest / 48;
    const int ks2   = frow >> 3;
    const int mtile = frow & 7;

    uint4 v;
    uint32_t* o = &v.x;
#pragma unroll
    for (int rg = 0; rg < 4; ++rg) {
        const int row = (lane >> 2) + 8 * (rg & 1);
        const int kb  = q * 32 + ks2 * 16 + 2 * (lane & 3) + 8 * (rg >> 1);
        const int co  = cb * 128 + mtile * 16 + row;
        const float w0 = w[(size_t)co * 1536 + kb];
        const float w1 = w[(size_t)co * 1536 + kb + 1];
        o[rg] = pack_f16x2(w0, w1);
    }
    reinterpret_cast<uint4*>(wp)[tid] = v;
}

// ---------------------------------------------------------------------------
// Act v3 (register-window upsample); plain fp32 output.
// ---------------------------------------------------------------------------
__global__ __launch_bounds__(256) void act_kernel(
    const float* __restrict__ in, float* __restrict__ out,
    const float* __restrict__ la, const float* __restrict__ lb,
    const float* __restrict__ fup, const float* __restrict__ fdn)
{
    __shared__ __align__(16) float sx[1040];
    __shared__ __align__(16) float sv[2064];
    __shared__ float su[12], sd[12];

    const int row = blockIdx.y;
    const int c   = row & (CCH - 1);
    const int t0  = blockIdx.x * 1024;
    const int tid = threadIdx.x;

    if (tid < 12) { su[tid] = fup[tid]; sd[tid] = fdn[tid]; }

    const float* xrow = in + (size_t)row * T_LEN;
#pragma unroll
    for (int it = 0; it < 5; ++it) {
        const int i = it * 256 + tid;
        if (i < 1040) {
            int g = t0 - 8 + i;
            g = min(max(g, 0), T_LEN - 1);
            sx[i] = xrow[g];
        }
    }
    __syncthreads();

    const float alpha = expf(la[c]);
    const float invb  = 1.0f / (expf(lb[c]) + 1e-9f);

    float u0=su[0],u1=su[1],u2=su[2],u3=su[3],u4=su[4],u5=su[5],
          u6=su[6],u7=su[7],u8=su[8],u9=su[9],u10=su[10],u11=su[11];

    {
        float xr[12];
        const float4 a0 = *reinterpret_cast<const float4*>(&sx[tid * 4]);
        const float4 a1 = *reinterpret_cast<const float4*>(&sx[tid * 4 + 4]);
        const float4 a2 = *reinterpret_cast<const float4*>(&sx[tid * 4 + 8]);
        xr[0]=a0.x; xr[1]=a0.y; xr[2]=a0.z; xr[3]=a0.w;
        xr[4]=a1.x; xr[5]=a1.y; xr[6]=a1.z; xr[7]=a1.w;
        xr[8]=a2.x; xr[9]=a2.y; xr[10]=a2.z; xr[11]=a2.w;

        float v[8];
#pragma unroll
        for (int m = 0; m < 4; ++m) {
            float ua = u0*xr[8+m] + u2*xr[7+m] + u4*xr[6+m]
                     + u6*xr[5+m] + u8*xr[4+m] + u10*xr[3+m];
            float ub = u1*xr[8+m] + u3*xr[7+m] + u5*xr[6+m]
                     + u7*xr[5+m] + u9*xr[4+m] + u11*xr[3+m];
            ua *= 2.0f; ub *= 2.0f;
            const float sa = __sinf(ua * alpha);
            const float sb = __sinf(ub * alpha);
            v[2*m]   = ua + sa * sa * invb;
            v[2*m+1] = ub + sb * sb * invb;
        }
        float4 o0, o1;
        o0.x=v[0]; o0.y=v[1]; o0.z=v[2]; o0.w=v[3];
        o1.x=v[4]; o1.y=v[5]; o1.z=v[6]; o1.w=v[7];
        *reinterpret_cast<float4*>(&sv[tid * 8])     = o0;
        *reinterpret_cast<float4*>(&sv[tid * 8 + 4]) = o1;
    }
    if (tid < 16) {
        const int i = 2048 + tid;
        const int tp = 2 * t0 - 5 + i;
        const int sx_off = 8 - t0;
        float u;
        if (tp & 1) {
            const int h = (tp + 5) >> 1;
            const float* p = &sx[h + sx_off];
            u = u0*p[0] + u2*p[-1] + u4*p[-2] + u6*p[-3] + u8*p[-4] + u10*p[-5];
        } else {
            const int h = tp >> 1;
            const float* p = &sx[h + sx_off];
            u = u1*p[2] + u3*p[1] + u5*p[0] + u7*p[-1] + u9*p[-2] + u11*p[-3];
        }
        u *= 2.0f;
        const float s = __sinf(u * alpha);
        sv[i] = u + s * s * invb;
    }
    __syncthreads();

    if (t0 == 0 && tid < 5) sv[tid] = sv[5];
    if (t0 == T_LEN - 1024 && tid < 11) sv[2053 + tid] = sv[2052];
    __syncthreads();

    {
        float d0=sd[0],d1=sd[1],d2=sd[2],d3=sd[3],d4=sd[4],d5=sd[5],
              d6=sd[6],d7=sd[7],d8=sd[8],d9=sd[9],d10=sd[10],d11=sd[11];
        const float4 w0 = *reinterpret_cast<const float4*>(&sv[tid * 8]);
        const float4 w1 = *reinterpret_cast<const float4*>(&sv[tid * 8 + 4]);
        const float4 w2 = *reinterpret_cast<const float4*>(&sv[tid * 8 + 8]);
        const float4 w3 = *reinterpret_cast<const float4*>(&sv[tid * 8 + 12]);
        const float4 w4 = *reinterpret_cast<const float4*>(&sv[tid * 8 + 16]);
        float v[20];
        v[0]=w0.x; v[1]=w0.y; v[2]=w0.z; v[3]=w0.w;
        v[4]=w1.x; v[5]=w1.y; v[6]=w1.z; v[7]=w1.w;
        v[8]=w2.x; v[9]=w2.y; v[10]=w2.z; v[11]=w2.w;
        v[12]=w3.x; v[13]=w3.y; v[14]=w3.z; v[15]=w3.w;
        v[16]=w4.x; v[17]=w4.y; v[18]=w4.z; v[19]=w4.w;
        float z[4];
#pragma unroll
        for (int o = 0; o < 4; ++o) {
            const float* p = v + 2 * o;
            z[o] = d0*p[0] + d1*p[1] + d2*p[2] + d3*p[3] + d4*p[4] + d5*p[5]
                 + d6*p[6] + d7*p[7] + d8*p[8] + d9*p[9] + d10*p[10] + d11*p[11];
        }
        float4 r; r.x = z[0]; r.y = z[1]; r.z = z[2]; r.w = z[3];
        *reinterpret_cast<float4*>(out + (size_t)row * T_LEN + t0 + tid * 4) = r;
    }
}

// ---------------------------------------------------------------------------
// fp16 HMMA implicit-GEMM conv. Block 128co x 128t, 4 warps (2x2), warp 64x64.
// m16n8k16: K=16/mma. 32-k double-buffered stages (48 iters, 2 ksteps each).
// A: f16x2 fragments via cp.async. B: [k2(16)][t(128)] f16x2 smem, pitch 136.
// ---------------------------------------------------------------------------
#define KCHUNKS 48
#define BPITCH 136
#define ASTAGE_W 2048
#define BSTAGE_W (16 * BPITCH)              // 2176
#define STAGE_W  (ASTAGE_W + BSTAGE_W)      // 4224 words
#define CONV_SMEM (2 * STAGE_W * 4)         // 33792 B

// Fill B pairs: pair j holds k = k0+2j, k0+2j+1 (f16x2, low = even k).
// v(k) = in[ci(k)][t + kk(k) - 1], zero-padded at t-boundaries.
template <int R0>
__device__ __forceinline__ void fillB16(
    const float* __restrict__ src0,   // inb + ci_base*T + t0 + tid
    uint32_t dstB, bool lo_edge, bool hi_edge)
{
#pragma unroll
    for (int j = 0; j < 16; ++j) {
        const int e0 = R0 + 2 * j;
        const int e1 = e0 + 1;
        const int ci0 = e0 / 3, kk0 = e0 % 3;
        const int ci1 = e1 / 3, kk1 = e1 % 3;
        float v0 = 0.0f, v1 = 0.0f;
        if (!((kk0 == 0 && lo_edge) || (kk0 == 2 && hi_edge)))
            v0 = __ldg(src0 + (size_t)ci0 * T_LEN + kk0 - 1);
        if (!((kk1 == 0 && lo_edge) || (kk1 == 2 && hi_edge)))
            v1 = __ldg(src0 + (size_t)ci1 * T_LEN + kk1 - 1);
        sts32(dstB + j * (BPITCH * 4), pack_f16x2(v0, v1));
    }
}

__global__ __launch_bounds__(128, 2)
void conv_tc(const float* __restrict__ in, const uint32_t* __restrict__ wperm,
             const float* __restrict__ bias, const float* __restrict__ resid,
             float* __restrict__ out)
{
    extern __shared__ uint32_t Ssm[];

    const int tid  = threadIdx.x;
    const int wid  = tid >> 5;
    const int lane = tid & 31;
    const int wr   = wid >> 1;
    const int wc   = wid & 1;
    const int b    = blockIdx.z;
    const int cb   = blockIdx.y;
    const int co0  = cb * 128;
    const int t0   = blockIdx.x * 128;
    const float* inb = in + (size_t)b * CCH * T_LEN;

    const bool lo_edge = (t0 + tid == 0);
    const bool hi_edge = (t0 + tid == T_LEN - 1);

    float acc[4][8][4];
#pragma unroll
    for (int i = 0; i < 4; i++)
#pragma unroll
        for (int j = 0; j < 8; j++)
#pragma unroll
            for (int r = 0; r < 4; r++) acc[i][j][r] = 0.0f;

    const uint32_t smem0 = smem_u32(Ssm);
    const float* src0 = inb + t0 + tid;   // + ci_base*T added per stage

    auto fill = [&](int q, int s) {
        // A: 512 uint4/stage, 4 cp.async.16 per thread
        const uint4* Asrc = reinterpret_cast<const uint4*>(wperm)
                          + ((size_t)(cb * 48 + q)) * 512 + tid;
        const uint32_t dstA = smem0 + s * (STAGE_W * 4) + tid * 16;
#pragma unroll
        for (int it = 0; it < 4; ++it)
            cp_async16(dstA + it * 2048, Asrc + it * 128);
        cp_commit();
        // B
        const int k0 = q * 32;
        const int ci_base = k0 / 3;
        const int r0 = k0 - 3 * ci_base;    // (2q)%3
        const uint32_t dstB = smem0 + (s * STAGE_W + ASTAGE_W + tid) * 4;
        const float* sp = src0 + (size_t)ci_base * T_LEN;
        if (r0 == 0)      fillB16<0>(sp, dstB, lo_edge, hi_edge);
        else if (r0 == 1) fillB16<1>(sp, dstB, lo_edge, hi_edge);
        else              fillB16<2>(sp, dstB, lo_edge, hi_edge);
    };

    fill(0, 0);

    for (int q = 0; q < KCHUNKS; ++q) {
        const int s = q & 1;
        cp_wait<0>();
        __syncthreads();
        if (q + 1 < KCHUNKS) fill(q + 1, s ^ 1);

        const uint32_t* As = Ssm + s * STAGE_W;
        const uint32_t* Bs = As + ASTAGE_W;
#pragma unroll
        for (int ks = 0; ks < 2; ++ks) {
            uint4 afr[4];
#pragma unroll
            for (int mt = 0; mt < 4; ++mt)
                afr[mt] = *reinterpret_cast<const uint4*>(
                    As + ((ks * 8 + wr * 4 + mt) * 32 + lane) * 4);
            uint2 bfr[8];
            const uint32_t* brow = Bs + (ks * 8 + (lane & 3)) * BPITCH
                                  + wc * 64 + (lane >> 2);
#pragma unroll
            for (int nt = 0; nt < 8; ++nt) {
                bfr[nt].x = brow[nt * 8];
                bfr[nt].y = brow[nt * 8 + 4 * BPITCH];
            }
#pragma unroll
            for (int mt = 0; mt < 4; ++mt)
#pragma unroll
                for (int nt = 0; nt < 8; ++nt)
                    mma_f16(acc[mt][nt],
                            reinterpret_cast<const uint32_t*>(&afr[mt]),
                            reinterpret_cast<const uint32_t*>(&bfr[nt]));
        }
    }

    __syncthreads();

    // ---- epilogue (same D fragment layout as m16n8k8) ----
    const int gid = lane >> 2;
    const int tig = lane & 3;
#pragma unroll
    for (int mt = 0; mt < 4; ++mt) {
#pragma unroll
        for (int half = 0; half < 2; ++half) {
            const int co = co0 + wr * 64 + mt * 16 + gid + half * 8;
            const float bv = __ldg(bias + co);
            float* orow = out + ((size_t)b * CCH + co) * T_LEN + t0 + wc * 64;
            const float* rrow = resid
                ? resid + ((size_t)b * CCH + co) * T_LEN + t0 + wc * 64 : nullptr;
#pragma unroll
            for (int nt = 0; nt < 8; ++nt) {
                const int n = nt * 8 + tig * 2;
                float lo = acc[mt][nt][half * 2 + 0] + bv;
                float hi = acc[mt][nt][half * 2 + 1] + bv;
                if (rrow) {
                    float2 rv = *reinterpret_cast<const float2*>(rrow + n);
                    lo += rv.x; hi += rv.y;
                }
                float2 v; v.x = lo; v.y = hi;
                *reinterpret_cast<float2*>(orow + n) = v;
            }
        }
    }
}

// ---------------------------------------------------------------------------
extern "C" void kernel_launch(void* const* d_in, const int* in_sizes, int n_in,
                              void* d_out, int out_size)
{
    const float* x    = (const float*)d_in[0];
    const float* a1a  = (const float*)d_in[1];
    const float* a1b  = (const float*)d_in[2];
    const float* a2a  = (const float*)d_in[3];
    const float* a2b  = (const float*)d_in[4];
    const float* c1w  = (const float*)d_in[5];
    const float* c1b  = (const float*)d_in[6];
    const float* c2w  = (const float*)d_in[7];
    const float* c2b  = (const float*)d_in[8];
    const float* fup  = (const float*)d_in[9];
    const float* fdn  = (const float*)d_in[10];
    float* out = (float*)d_out;

    float *g1, *g2;
    uint32_t *wp1, *wp2;
    cudaGetSymbolAddress((void**)&g1, g_buf1);
    cudaGetSymbolAddress((void**)&g2, g_buf2);
    cudaGetSymbolAddress((void**)&wp1, g_wperm1);
    cudaGetSymbolAddress((void**)&wp2, g_wperm2);

    cudaFuncSetAttribute(conv_tc, cudaFuncAttributeMaxDynamicSharedMemorySize, CONV_SMEM);

    dim3 gAct(T_LEN / 1024, BATCH * CCH);
    dim3 gConv(T_LEN / 128, CCH / 128, BATCH);

    permute_w<<<384, 256>>>(c1w, wp1);
    permute_w<<<384, 256>>>(c2w, wp2);

    act_kernel<<<gAct, 256>>>(x, g1, a1a, a1b, fup, fdn);
    conv_tc<<<gConv, 128, CONV_SMEM>>>(g1, wp1, c1b, nullptr, g2);
    act_kernel<<<gAct, 256>>>(g2, g1, a2a, a2b, fup, fdn);
    conv_tc<<<gConv, 128, CONV_SMEM>>>(g1, wp2, c2b, x, out);
}

// round 10
// speedup vs baseline: 6.8751x; 1.2848x over previous
#include <cuda_runtime.h>
#include <cuda_fp16.h>
#include <cstdint>

#define T_LEN 8192
#define CCH   512
#define BATCH 8
#define NELEM (BATCH * CCH * T_LEN)

__device__ float  g_buf1[NELEM];            // act output (f32, [B][C][T])
__device__ float  g_buf2[NELEM];            // conv1 output (f32, [B][C][T])
__device__ __half g_bufT[NELEM];            // transposed act output (f16, [B][T][C])

// Pre-permuted f16 weights, fragment order:
// u = (((cb*16 + st)*6 + (kk*2+ks))*8 + mt)*32 + lane   (uint4 each)
#define WPERM_U4 (4 * 16 * 6 * 8 * 32)     // 98304 uint4 = 1.5 MB
__device__ uint4 g_wperm1[WPERM_U4];
__device__ uint4 g_wperm2[WPERM_U4];

// ---------------------------------------------------------------------------
__device__ __forceinline__ uint32_t smem_u32(const void* p) {
    uint32_t a;
    asm("{ .reg .u64 t; cvta.to.shared.u64 t, %1; cvt.u32.u64 %0, t; }"
        : "=r"(a) : "l"(p));
    return a;
}
__device__ __forceinline__ uint32_t pack_f16x2(float lo, float hi) {
    uint32_t r;
    asm("cvt.rn.f16x2.f32 %0, %1, %2;" : "=r"(r) : "f"(hi), "f"(lo));
    return r;
}
__device__ __forceinline__ void cp_async16(uint32_t dst, const void* src) {
    asm volatile("cp.async.cg.shared.global [%0], [%1], 16;"
                 :: "r"(dst), "l"(src));
}
__device__ __forceinline__ void cp_async16s(uint32_t dst, const void* src, uint32_t sz) {
    asm volatile("cp.async.cg.shared.global [%0], [%1], 16, %2;"
                 :: "r"(dst), "l"(src), "r"(sz));
}
__device__ __forceinline__ void cp_commit() {
    asm volatile("cp.async.commit_group;" ::: "memory");
}
template <int N>
__device__ __forceinline__ void cp_wait() {
    asm volatile("cp.async.wait_group %0;" :: "n"(N) : "memory");
}
__device__ __forceinline__ void mma_f16(float* d, const uint32_t* a, const uint32_t* b) {
    asm volatile(
        "mma.sync.aligned.m16n8k16.row.col.f32.f16.f16.f32 "
        "{%0,%1,%2,%3}, {%4,%5,%6,%7}, {%8,%9}, {%0,%1,%2,%3};"
        : "+f"(d[0]), "+f"(d[1]), "+f"(d[2]), "+f"(d[3])
        : "r"(a[0]), "r"(a[1]), "r"(a[2]), "r"(a[3]), "r"(b[0]), "r"(b[1]));
}

// ---------------------------------------------------------------------------
// Weight permutation: K-dim = ci (3 separate kk GEMMs).
// a-frag reg rg: m8 = (lane>>2)+8*(rg&1); ci = base + 2*(lane&3) + 8*(rg>>1) + {0,1}
// ---------------------------------------------------------------------------
__global__ __launch_bounds__(256) void permute_w(
    const float* __restrict__ w, uint4* __restrict__ wp)
{
    const int u = blockIdx.x * 256 + threadIdx.x;   // 0..98303
    const int lane = u & 31;
    const int rest = u >> 5;
    const int mt = rest & 7;
    const int g  = (rest >> 3) % 6;
    const int sc = (rest >> 3) / 6;
    const int ks = g & 1;
    const int kk = g >> 1;
    const int st = sc & 15;
    const int cb = sc >> 4;

    uint4 v;
    uint32_t* o = &v.x;
#pragma unroll
    for (int rg = 0; rg < 4; ++rg) {
        const int m8 = (lane >> 2) + 8 * (rg & 1);
        const int ci = st * 32 + ks * 16 + 2 * (lane & 3) + 8 * (rg >> 1);
        const int co = cb * 128 + mt * 16 + m8;
        const float w0 = w[(size_t)co * 1536 + ci * 3 + kk];
        const float w1 = w[(size_t)co * 1536 + (ci + 1) * 3 + kk];
        o[rg] = pack_f16x2(w0, w1);
    }
    wp[u] = v;
}

// ---------------------------------------------------------------------------
// Act v3 (register-window upsample); f32 output [B][C][T].
// ---------------------------------------------------------------------------
__global__ __launch_bounds__(256) void act_kernel(
    const float* __restrict__ in, float* __restrict__ out,
    const float* __restrict__ la, const float* __restrict__ lb,
    const float* __restrict__ fup, const float* __restrict__ fdn)
{
    __shared__ __align__(16) float sx[1040];
    __shared__ __align__(16) float sv[2064];
    __shared__ float su[12], sd[12];

    const int row = blockIdx.y;
    const int c   = row & (CCH - 1);
    const int t0  = blockIdx.x * 1024;
    const int tid = threadIdx.x;

    if (tid < 12) { su[tid] = fup[tid]; sd[tid] = fdn[tid]; }

    const float* xrow = in + (size_t)row * T_LEN;
#pragma unroll
    for (int it = 0; it < 5; ++it) {
        const int i = it * 256 + tid;
        if (i < 1040) {
            int g = t0 - 8 + i;
            g = min(max(g, 0), T_LEN - 1);
            sx[i] = xrow[g];
        }
    }
    __syncthreads();

    const float alpha = expf(la[c]);
    const float invb  = 1.0f / (expf(lb[c]) + 1e-9f);

    float u0=su[0],u1=su[1],u2=su[2],u3=su[3],u4=su[4],u5=su[5],
          u6=su[6],u7=su[7],u8=su[8],u9=su[9],u10=su[10],u11=su[11];

    {
        float xr[12];
        const float4 a0 = *reinterpret_cast<const float4*>(&sx[tid * 4]);
        const float4 a1 = *reinterpret_cast<const float4*>(&sx[tid * 4 + 4]);
        const float4 a2 = *reinterpret_cast<const float4*>(&sx[tid * 4 + 8]);
        xr[0]=a0.x; xr[1]=a0.y; xr[2]=a0.z; xr[3]=a0.w;
        xr[4]=a1.x; xr[5]=a1.y; xr[6]=a1.z; xr[7]=a1.w;
        xr[8]=a2.x; xr[9]=a2.y; xr[10]=a2.z; xr[11]=a2.w;

        float v[8];
#pragma unroll
        for (int m = 0; m < 4; ++m) {
            float ua = u0*xr[8+m] + u2*xr[7+m] + u4*xr[6+m]
                     + u6*xr[5+m] + u8*xr[4+m] + u10*xr[3+m];
            float ub = u1*xr[8+m] + u3*xr[7+m] + u5*xr[6+m]
                     + u7*xr[5+m] + u9*xr[4+m] + u11*xr[3+m];
            ua *= 2.0f; ub *= 2.0f;
            const float sa = __sinf(ua * alpha);
            const float sb = __sinf(ub * alpha);
            v[2*m]   = ua + sa * sa * invb;
            v[2*m+1] = ub + sb * sb * invb;
        }
        float4 o0, o1;
        o0.x=v[0]; o0.y=v[1]; o0.z=v[2]; o0.w=v[3];
        o1.x=v[4]; o1.y=v[5]; o1.z=v[6]; o1.w=v[7];
        *reinterpret_cast<float4*>(&sv[tid * 8])     = o0;
        *reinterpret_cast<float4*>(&sv[tid * 8 + 4]) = o1;
    }
    if (tid < 16) {
        const int i = 2048 + tid;
        const int tp = 2 * t0 - 5 + i;
        const int sx_off = 8 - t0;
        float u;
        if (tp & 1) {
            const int h = (tp + 5) >> 1;
            const float* p = &sx[h + sx_off];
            u = u0*p[0] + u2*p[-1] + u4*p[-2] + u6*p[-3] + u8*p[-4] + u10*p[-5];
        } else {
            const int h = tp >> 1;
            const float* p = &sx[h + sx_off];
            u = u1*p[2] + u3*p[1] + u5*p[0] + u7*p[-1] + u9*p[-2] + u11*p[-3];
        }
        u *= 2.0f;
        const float s = __sinf(u * alpha);
        sv[i] = u + s * s * invb;
    }
    __syncthreads();

    if (t0 == 0 && tid < 5) sv[tid] = sv[5];
    if (t0 == T_LEN - 1024 && tid < 11) sv[2053 + tid] = sv[2052];
    __syncthreads();

    {
        float d0=sd[0],d1=sd[1],d2=sd[2],d3=sd[3],d4=sd[4],d5=sd[5],
              d6=sd[6],d7=sd[7],d8=sd[8],d9=sd[9],d10=sd[10],d11=sd[11];
        const float4 w0 = *reinterpret_cast<const float4*>(&sv[tid * 8]);
        const float4 w1 = *reinterpret_cast<const float4*>(&sv[tid * 8 + 4]);
        const float4 w2 = *reinterpret_cast<const float4*>(&sv[tid * 8 + 8]);
        const float4 w3 = *reinterpret_cast<const float4*>(&sv[tid * 8 + 12]);
        const float4 w4 = *reinterpret_cast<const float4*>(&sv[tid * 8 + 16]);
        float v[20];
        v[0]=w0.x; v[1]=w0.y; v[2]=w0.z; v[3]=w0.w;
        v[4]=w1.x; v[5]=w1.y; v[6]=w1.z; v[7]=w1.w;
        v[8]=w2.x; v[9]=w2.y; v[10]=w2.z; v[11]=w2.w;
        v[12]=w3.x; v[13]=w3.y; v[14]=w3.z; v[15]=w3.w;
        v[16]=w4.x; v[17]=w4.y; v[18]=w4.z; v[19]=w4.w;
        float z[4];
#pragma unroll
        for (int o = 0; o < 4; ++o) {
            const float* p = v + 2 * o;
            z[o] = d0*p[0] + d1*p[1] + d2*p[2] + d3*p[3] + d4*p[4] + d5*p[5]
                 + d6*p[6] + d7*p[7] + d8*p[8] + d9*p[9] + d10*p[10] + d11*p[11];
        }
        float4 r; r.x = z[0]; r.y = z[1]; r.z = z[2]; r.w = z[3];
        *reinterpret_cast<float4*>(out + (size_t)row * T_LEN + t0 + tid * 4) = r;
    }
}

// ---------------------------------------------------------------------------
// Transpose + cvt: f32 [B][C][T] -> f16 [B][T][C].  Tile 32c x 64t.
// ---------------------------------------------------------------------------
__global__ __launch_bounds__(256) void transpose_cvt(
    const float* __restrict__ in, __half* __restrict__ out)
{
    __shared__ float sx[32][65];
    const int t0 = blockIdx.x * 64;
    const int c0 = blockIdx.y * 32;
    const int b  = blockIdx.z;
    const int tid = threadIdx.x;

    {
        const int cl = tid >> 3;
        const int t4 = (tid & 7) * 8;
        const float* src = in + ((size_t)(b * CCH + c0 + cl)) * T_LEN + t0 + t4;
        const float4 v0 = *reinterpret_cast<const float4*>(src);
        const float4 v1 = *reinterpret_cast<const float4*>(src + 4);
        sx[cl][t4+0]=v0.x; sx[cl][t4+1]=v0.y; sx[cl][t4+2]=v0.z; sx[cl][t4+3]=v0.w;
        sx[cl][t4+4]=v1.x; sx[cl][t4+5]=v1.y; sx[cl][t4+6]=v1.z; sx[cl][t4+7]=v1.w;
    }
    __syncthreads();
    {
        const int tl = tid >> 2;
        const int cg = (tid & 3) * 8;
        uint4 o;
        o.x = pack_f16x2(sx[cg+0][tl], sx[cg+1][tl]);
        o.y = pack_f16x2(sx[cg+2][tl], sx[cg+3][tl]);
        o.z = pack_f16x2(sx[cg+4][tl], sx[cg+5][tl]);
        o.w = pack_f16x2(sx[cg+6][tl], sx[cg+7][tl]);
        *reinterpret_cast<uint4*>(out + ((size_t)(b * T_LEN + t0 + tl)) * CCH + c0 + cg) = o;
    }
}

// ---------------------------------------------------------------------------
// fp16 HMMA conv as 3 shifted GEMMs over K=ci. Block 128co x 128t, 4 warps.
// Per 32-ci stage: A = 6 ksteps of frags (24KB), B = shared Xt tile, 130 rows
// (t0-1..t0+128) x 32 ci f16, row pitch 20 words (80B). All fill via cp.async.
// ---------------------------------------------------------------------------
#define NST 16
#define BP  20                               // B row pitch in words
#define ASTAGE_W 6144                        // 24576 B
#define BSTAGE_W (130 * BP)                  // 2600 words
#define STAGE_W  (ASTAGE_W + BSTAGE_W)       // 8744 words
#define CONV_SMEM (2 * STAGE_W * 4)          // 69952 B

__global__ __launch_bounds__(128, 2)
void conv_tc(const __half* __restrict__ xt, const uint4* __restrict__ wperm,
             const float* __restrict__ bias, const float* __restrict__ resid,
             float* __restrict__ out)
{
    extern __shared__ uint32_t Ssm[];

    const int tid  = threadIdx.x;
    const int wid  = tid >> 5;
    const int lane = tid & 31;
    const int wr   = wid >> 1;
    const int wc   = wid & 1;
    const int b    = blockIdx.z;
    const int cb   = blockIdx.y;
    const int co0  = cb * 128;
    const int t0   = blockIdx.x * 128;

    float acc[4][8][4];
#pragma unroll
    for (int i = 0; i < 4; i++)
#pragma unroll
        for (int j = 0; j < 8; j++)
#pragma unroll
            for (int r = 0; r < 4; r++) acc[i][j][r] = 0.0f;

    const uint32_t smem0 = smem_u32(Ssm);
    const char* browg = reinterpret_cast<const char*>(
        xt + ((size_t)(b * T_LEN + t0 - 1)) * CCH);

    auto fill = [&](int st, int s) {
        // A: 1536 uint4 per stage, contiguous
        const uint4* Asrc = wperm + ((size_t)(cb * 16 + st)) * 1536 + tid;
        const uint32_t dstA = smem0 + s * (STAGE_W * 4) + tid * 16;
#pragma unroll
        for (int it = 0; it < 12; ++it)
            cp_async16(dstA + it * 2048, Asrc + it * 128);
        // B: 130 rows x 64B = 520 cp16
        const uint32_t dstB = smem0 + s * (STAGE_W * 4) + ASTAGE_W * 4;
        const char* bs = browg + st * 64;
#pragma unroll
        for (int it = 0; it < 5; ++it) {
            const int idx = tid + it * 128;
            if (idx < 520) {
                const int row = idx >> 2, seg = idx & 3;
                const int tg = t0 - 1 + row;
                const uint32_t sz = (tg >= 0 && tg < T_LEN) ? 16u : 0u;
                cp_async16s(dstB + row * (BP * 4) + seg * 16,
                            bs + (size_t)row * (CCH * 2) + seg * 16, sz);
            }
        }
        cp_commit();
    };

    fill(0, 0);

    for (int st = 0; st < NST; ++st) {
        const int s = st & 1;
        cp_wait<0>();
        __syncthreads();
        if (st + 1 < NST) fill(st + 1, s ^ 1);

        const uint32_t* As = Ssm + s * STAGE_W;
        const uint32_t* Bs = As + ASTAGE_W;
        const uint32_t* Bl = Bs + (wc * 64 + (lane >> 2)) * BP + (lane & 3);
#pragma unroll
        for (int kk = 0; kk < 3; ++kk) {
#pragma unroll
            for (int ks = 0; ks < 2; ++ks) {
                uint4 afr[4];
#pragma unroll
                for (int mt = 0; mt < 4; ++mt)
                    afr[mt] = *reinterpret_cast<const uint4*>(
                        As + (((kk * 2 + ks) * 8 + wr * 4 + mt) * 32 + lane) * 4);
                uint2 bfr[8];
                const uint32_t* brow = Bl + kk * BP + ks * 8;
#pragma unroll
                for (int nt = 0; nt < 8; ++nt) {
                    bfr[nt].x = brow[nt * (8 * BP)];
                    bfr[nt].y = brow[nt * (8 * BP) + 4];
                }
#pragma unroll
                for (int mt = 0; mt < 4; ++mt)
#pragma unroll
                    for (int nt = 0; nt < 8; ++nt)
                        mma_f16(acc[mt][nt],
                                reinterpret_cast<const uint32_t*>(&afr[mt]),
                                reinterpret_cast<const uint32_t*>(&bfr[nt]));
            }
        }
    }

    __syncthreads();

    // ---- epilogue ----
    const int gid = lane >> 2;
    const int tig = lane & 3;
#pragma unroll
    for (int mt = 0; mt < 4; ++mt) {
#pragma unroll
        for (int half = 0; half < 2; ++half) {
            const int co = co0 + wr * 64 + mt * 16 + gid + half * 8;
            const float bv = __ldg(bias + co);
            float* orow = out + ((size_t)b * CCH + co) * T_LEN + t0 + wc * 64;
            const float* rrow = resid
                ? resid + ((size_t)b * CCH + co) * T_LEN + t0 + wc * 64 : nullptr;
#pragma unroll
            for (int nt = 0; nt < 8; ++nt) {
                const int n = nt * 8 + tig * 2;
                float lo = acc[mt][nt][half * 2 + 0] + bv;
                float hi = acc[mt][nt][half * 2 + 1] + bv;
                if (rrow) {
                    float2 rv = *reinterpret_cast<const float2*>(rrow + n);
                    lo += rv.x; hi += rv.y;
                }
                float2 v; v.x = lo; v.y = hi;
                *reinterpret_cast<float2*>(orow + n) = v;
            }
        }
    }
}

// ---------------------------------------------------------------------------
extern "C" void kernel_launch(void* const* d_in, const int* in_sizes, int n_in,
                              void* d_out, int out_size)
{
    const float* x    = (const float*)d_in[0];
    const float* a1a  = (const float*)d_in[1];
    const float* a1b  = (const float*)d_in[2];
    const float* a2a  = (const float*)d_in[3];
    const float* a2b  = (const float*)d_in[4];
    const float* c1w  = (const float*)d_in[5];
    const float* c1b  = (const float*)d_in[6];
    const float* c2w  = (const float*)d_in[7];
    const float* c2b  = (const float*)d_in[8];
    const float* fup  = (const float*)d_in[9];
    const float* fdn  = (const float*)d_in[10];
    float* out = (float*)d_out;

    float *g1, *g2;
    __half* gT;
    uint4 *wp1, *wp2;
    cudaGetSymbolAddress((void**)&g1, g_buf1);
    cudaGetSymbolAddress((void**)&g2, g_buf2);
    cudaGetSymbolAddress((void**)&gT, g_bufT);
    cudaGetSymbolAddress((void**)&wp1, g_wperm1);
    cudaGetSymbolAddress((void**)&wp2, g_wperm2);

    cudaFuncSetAttribute(conv_tc, cudaFuncAttributeMaxDynamicSharedMemorySize, CONV_SMEM);

    dim3 gAct(T_LEN / 1024, BATCH * CCH);
    dim3 gTr(T_LEN / 64, CCH / 32, BATCH);
    dim3 gConv(T_LEN / 128, CCH / 128, BATCH);

    permute_w<<<384, 256>>>(c1w, wp1);
    permute_w<<<384, 256>>>(c2w, wp2);

    act_kernel<<<gAct, 256>>>(x, g1, a1a, a1b, fup, fdn);
    transpose_cvt<<<gTr, 256>>>(g1, gT);
    conv_tc<<<gConv, 128, CONV_SMEM>>>(gT, wp1, c1b, nullptr, g2);
    act_kernel<<<gAct, 256>>>(g2, g1, a2a, a2b, fup, fdn);
    transpose_cvt<<<gTr, 256>>>(g1, gT);
    conv_tc<<<gConv, 128, CONV_SMEM>>>(gT, wp2, c2b, x, out);
}